// round 14
// baseline (speedup 1.0000x reference)
#include <cuda_runtime.h>
#include <cuda_fp16.h>
#include <math.h>
#include <stdint.h>

// Problem dims
#define BB 32
#define TT 256
#define CC 384
#define LL 6
#define NH 6
#define HD 64
#define VV 32000
#define MM (BB*TT)      // 8192
#define FF (4*CC)       // 1536

// fp16 weight scratch layout (uint32 = half2 units), stored TRANSPOSED [N][Kp]
#define OFF16_WQ 0
#define OFF16_WK 442368
#define OFF16_WV 884736
#define OFF16_WO 1327104
#define OFF16_W1 1769472
#define OFF16_W2 3538944
#define OFF16_LM 5308416
#define WT16_TOTAL 11452416

// Scratch (device globals; no allocations allowed)
__device__ float    g_x[MM*CC];          // residual stream (f32)
__device__ uint32_t g_h[MM*CC/2];        // LN output (fp16 packed, Kp=192)
__device__ uint32_t g_q[MM*CC];          // tf32 (attention input)
__device__ uint32_t g_k[MM*CC];
__device__ uint32_t g_v[MM*CC];
__device__ uint32_t g_att[MM*CC/2];      // fp16 packed
__device__ uint32_t g_u[MM*FF/2];        // fp16 packed
__device__ uint32_t g_wt[WT16_TOTAL];    // fp16 transposed weights

// ---------------------------------------------------------------------------
// Helpers
// ---------------------------------------------------------------------------
__device__ __forceinline__ uint32_t f2tf(float f) {
    uint32_t u;
    asm("cvt.rna.tf32.f32 %0, %1;" : "=r"(u) : "f"(f));
    return u;
}

__device__ __forceinline__ uint32_t packh2(float lo, float hi) {
    __half2 h = __floats2half2_rn(lo, hi);
    return *(uint32_t*)&h;
}

__device__ __forceinline__ void mma_tf32(float* c, const uint32_t* a, const uint32_t* b) {
    asm volatile(
        "mma.sync.aligned.m16n8k8.row.col.f32.tf32.tf32.f32 "
        "{%0,%1,%2,%3}, {%4,%5,%6,%7}, {%8,%9}, {%0,%1,%2,%3};"
        : "+f"(c[0]), "+f"(c[1]), "+f"(c[2]), "+f"(c[3])
        : "r"(a[0]), "r"(a[1]), "r"(a[2]), "r"(a[3]),
          "r"(b[0]), "r"(b[1]));
}

__device__ __forceinline__ void mma_f16(float* c, const uint32_t* a, const uint32_t* b) {
    asm volatile(
        "mma.sync.aligned.m16n8k16.row.col.f32.f16.f16.f32 "
        "{%0,%1,%2,%3}, {%4,%5,%6,%7}, {%8,%9}, {%0,%1,%2,%3};"
        : "+f"(c[0]), "+f"(c[1]), "+f"(c[2]), "+f"(c[3])
        : "r"(a[0]), "r"(a[1]), "r"(a[2]), "r"(a[3]),
          "r"(b[0]), "r"(b[1]));
}

__device__ __forceinline__ void cp_async16(void* sptr, const void* gptr) {
    uint32_t sa = (uint32_t)__cvta_generic_to_shared(sptr);
    asm volatile("cp.async.cg.shared.global [%0], [%1], 16;\n" :: "r"(sa), "l"(gptr));
}
#define CP_COMMIT() asm volatile("cp.async.commit_group;\n" ::: "memory")
#define CP_WAIT0()  asm volatile("cp.async.wait_group 0;\n" ::: "memory")
#define CP_WAIT1()  asm volatile("cp.async.wait_group 1;\n" ::: "memory")

// ---------------------------------------------------------------------------
// Fused transpose + fp16 convert of ALL weights, one launch.
// ---------------------------------------------------------------------------
#define R0 110592
#define R1 221184
#define R2 331776
#define R3 442368
#define R4 884736
#define R5 1327104
#define R6 2863104

__global__ void cvt_trans_kernel(const float* __restrict__ wq, const float* __restrict__ wk,
                                 const float* __restrict__ wv, const float* __restrict__ wo,
                                 const float* __restrict__ w1, const float* __restrict__ w2,
                                 const float* __restrict__ lm, uint32_t* __restrict__ wt)
{
    int f = blockIdx.x * blockDim.x + threadIdx.x;
    if (f >= R6) return;
    const float* src; uint32_t* dst; int K, N, local;
    if (f < R0)      { src = wq; dst = wt + OFF16_WQ; K = CC; N = CC; local = f; }
    else if (f < R1) { src = wk; dst = wt + OFF16_WK; K = CC; N = CC; local = f - R0; }
    else if (f < R2) { src = wv; dst = wt + OFF16_WV; K = CC; N = CC; local = f - R1; }
    else if (f < R3) { src = wo; dst = wt + OFF16_WO; K = CC; N = CC; local = f - R2; }
    else if (f < R4) { src = w1; dst = wt + OFF16_W1; K = CC; N = FF; local = f - R3; }
    else if (f < R5) { src = w2; dst = wt + OFF16_W2; K = FF; N = CC; local = f - R4; }
    else             { src = lm; dst = wt + OFF16_LM; K = CC; N = VV; local = f - R5; }

    int Kp    = K >> 1;
    int PL    = (K >> 3) * N;
    int layer = local / PL;
    int r     = local - layer * PL;
    int kg    = r / N;
    int n     = r - kg * N;

    const float* s0 = src + (size_t)layer*K*N + (size_t)(kg*8)*N + n;
    float s[8];
#pragma unroll
    for (int t = 0; t < 8; t++) s[t] = s0[(size_t)t*N];
    uint32_t* d = dst + (size_t)layer*N*Kp + (size_t)n*Kp + kg*4;
    uint4 o;
    o.x = packh2(s[0], s[1]);
    o.y = packh2(s[2], s[3]);
    o.z = packh2(s[4], s[5]);
    o.w = packh2(s[6], s[7]);
    *(uint4*)d = o;
}

// ---------------------------------------------------------------------------
// Embedding (f32 residual stream)
// ---------------------------------------------------------------------------
__global__ void embed_kernel(const int* __restrict__ idx,
                             const float* __restrict__ tok,
                             const float* __restrict__ pos,
                             float* __restrict__ X)
{
    int i = blockIdx.x * blockDim.x + threadIdx.x;
    if (i >= MM * (CC/4)) return;
    int row = i / (CC/4);
    int c4  = i % (CC/4);
    int t   = idx[row];
    int p   = row & (TT-1);
    float4 a = *(const float4*)(tok + (size_t)t*CC + c4*4);
    float4 e = *(const float4*)(pos + (size_t)p*CC + c4*4);
    a.x += e.x; a.y += e.y; a.z += e.z; a.w += e.w;
    *(float4*)(X + (size_t)row*CC + c4*4) = a;
}

// ---------------------------------------------------------------------------
// LayerNorm: one warp per row; output fp16 packed.
// ---------------------------------------------------------------------------
__global__ void ln_kernel(const float* __restrict__ X,
                          const float* __restrict__ g,
                          const float* __restrict__ b,
                          uint32_t* __restrict__ Y)
{
    int row  = blockIdx.x * 8 + (threadIdx.x >> 5);
    int lane = threadIdx.x & 31;
    if (row >= MM) return;
    const float* x = X + (size_t)row*CC;
    float2 v[6];
    float s = 0.f, ss = 0.f;
#pragma unroll
    for (int j = 0; j < 6; j++) {
        int c = j*64 + 2*lane;
        v[j] = *(const float2*)(x + c);
        s  += v[j].x + v[j].y;
        ss += v[j].x*v[j].x + v[j].y*v[j].y;
    }
#pragma unroll
    for (int o = 16; o; o >>= 1) {
        s  += __shfl_xor_sync(0xFFFFFFFFu, s,  o);
        ss += __shfl_xor_sync(0xFFFFFFFFu, ss, o);
    }
    float mean = s  * (1.0f/CC);
    float var  = ss * (1.0f/CC) - mean*mean;
    float inv  = rsqrtf(var + 1e-5f);
    uint32_t* y = Y + (size_t)row*(CC/2);
#pragma unroll
    for (int j = 0; j < 6; j++) {
        int c = j*64 + 2*lane;
        float a0 = (v[j].x - mean)*inv*g[c    ] + b[c    ];
        float a1 = (v[j].y - mean)*inv*g[c + 1] + b[c + 1];
        y[j*32 + lane] = packh2(a0, a1);
    }
}

// ---------------------------------------------------------------------------
// FP16 GEMM: 128x128 tile, BK=32 (16 kp), 256 threads, 8 warps of 64x32
// (2 m-rows x 4 n-cols), 2-stage cp.async. ~110 regs -> 2 CTAs/SM
// -> 16 warps/SM (vs 8 before).
// OUTMODE: 0 = f32, 1 = tf32, 2 = fp16 packed.
// ---------------------------------------------------------------------------
struct GemmSmemH {
    uint32_t As[2][128][20];   // 20480 B
    uint32_t Bs[2][128][20];   // 20480 B
};
#define SMEM_GEMMH ((int)sizeof(GemmSmemH))   // 40960 bytes

template<bool RELU, bool RES, int OUTMODE>
__device__ __forceinline__
void gemm_core(GemmSmemH* sm,
               const uint32_t* __restrict__ A, const uint32_t* __restrict__ B,
               const float* __restrict__ bias, const float* __restrict__ res,
               void* __restrict__ Cv, int M, int N, int K, int bm, int bn)
{
    const int Kp   = K >> 1;
    const int tid  = threadIdx.x;
    const int lane = tid & 31;
    const int wid  = tid >> 5;
    const int wm = (wid & 1) * 64;     // 2 rows of warps
    const int wn = (wid >> 1) * 32;    // 4 cols of warps
    const int grp = lane >> 2;
    const int tg  = lane & 3;

    float acc[4][4][4];
#pragma unroll
    for (int mt = 0; mt < 4; mt++)
#pragma unroll
        for (int nt = 0; nt < 4; nt++)
#pragma unroll
            for (int e = 0; e < 4; e++) acc[mt][nt][e] = 0.f;

    auto issue = [&](int s, int k0p) {
#pragma unroll
        for (int p = 0; p < 2; p++) {          // A: 128 rows x 16 uints = 512 chunks
            int i  = tid + p*256;
            int r  = i >> 2;
            int c4 = (i & 3) * 4;
            cp_async16(&sm->As[s][r][c4], A + (size_t)(bm + r)*Kp + k0p + c4);
        }
#pragma unroll
        for (int p = 0; p < 2; p++) {          // B: 128 n x 16 uints
            int i  = tid + p*256;
            int r  = i >> 2;
            int c4 = (i & 3) * 4;
            cp_async16(&sm->Bs[s][r][c4], B + (size_t)(bn + r)*Kp + k0p + c4);
        }
        CP_COMMIT();
    };

    const int nIter = K >> 5;
    issue(0, 0);

    for (int it = 0; it < nIter; it++) {
        const int cur = it & 1;
        CP_WAIT0();
        __syncthreads();
        if (it + 1 < nIter) issue(cur ^ 1, (it + 1) << 4);

#pragma unroll
        for (int kps = 0; kps < 16; kps += 8) {
            uint32_t af[4][4], bf[4][2];
#pragma unroll
            for (int mt = 0; mt < 4; mt++) {
                int r = wm + mt*16 + grp;
                af[mt][0] = sm->As[cur][r    ][kps + tg    ];
                af[mt][1] = sm->As[cur][r + 8][kps + tg    ];
                af[mt][2] = sm->As[cur][r    ][kps + tg + 4];
                af[mt][3] = sm->As[cur][r + 8][kps + tg + 4];
            }
#pragma unroll
            for (int nt = 0; nt < 4; nt++) {
                int c = wn + nt*8 + grp;
                bf[nt][0] = sm->Bs[cur][c][kps + tg    ];
                bf[nt][1] = sm->Bs[cur][c][kps + tg + 4];
            }
#pragma unroll
            for (int mt = 0; mt < 4; mt++)
#pragma unroll
                for (int nt = 0; nt < 4; nt++)
                    mma_f16(acc[mt][nt], af[mt], bf[nt]);
        }
    }

    // Epilogue
#pragma unroll
    for (int mt = 0; mt < 4; mt++) {
        int r0 = bm + wm + mt*16 + grp;
        int r1 = r0 + 8;
#pragma unroll
        for (int nt = 0; nt < 4; nt++) {
            int c = bn + wn + nt*8 + tg*2;
            float o0x = acc[mt][nt][0], o0y = acc[mt][nt][1];
            float o1x = acc[mt][nt][2], o1y = acc[mt][nt][3];
            if (bias) {
                float bv0 = bias[c], bv1 = bias[c+1];
                o0x += bv0; o0y += bv1; o1x += bv0; o1y += bv1;
            }
            if (RES) {
                float2 ra = *(const float2*)(res + (size_t)r0*N + c);
                float2 rb = *(const float2*)(res + (size_t)r1*N + c);
                o0x += ra.x; o0y += ra.y; o1x += rb.x; o1y += rb.y;
            }
            if (RELU) {
                o0x = fmaxf(o0x, 0.f); o0y = fmaxf(o0y, 0.f);
                o1x = fmaxf(o1x, 0.f); o1y = fmaxf(o1y, 0.f);
            }
            if (OUTMODE == 0) {
                float* C = (float*)Cv;
                float2 w0 = {o0x, o0y};
                float2 w1 = {o1x, o1y};
                *(float2*)(C + (size_t)r0*N + c) = w0;
                *(float2*)(C + (size_t)r1*N + c) = w1;
            } else if (OUTMODE == 1) {
                uint32_t* C = (uint32_t*)Cv;
                uint2 w0 = {f2tf(o0x), f2tf(o0y)};
                uint2 w1 = {f2tf(o1x), f2tf(o1y)};
                *(uint2*)(C + (size_t)r0*N + c) = w0;
                *(uint2*)(C + (size_t)r1*N + c) = w1;
            } else {
                uint32_t* C = (uint32_t*)Cv;
                C[(size_t)r0*(N>>1) + (c>>1)] = packh2(o0x, o0y);
                C[(size_t)r1*(N>>1) + (c>>1)] = packh2(o1x, o1y);
            }
        }
    }
}

template<bool RELU, bool RES, int OUTMODE>
__global__ __launch_bounds__(256)
void tgemm(const uint32_t* __restrict__ A, const uint32_t* __restrict__ B,
           const float* __restrict__ bias, const float* __restrict__ res,
           void* __restrict__ C, int M, int N, int K)
{
    extern __shared__ GemmSmemH smg[];
    gemm_core<RELU, RES, OUTMODE>(smg, A, B, bias, res, C, M, N, K,
                                  blockIdx.y * 128, blockIdx.x * 128);
}

// Fused QKV: grid.x = 9 (3 matrices x 3 col-tiles), grid.y = 64. tf32 out.
__global__ __launch_bounds__(256)
void qkv_gemm(const uint32_t* __restrict__ A,
              const uint32_t* __restrict__ Wq, const uint32_t* __restrict__ Wk,
              const uint32_t* __restrict__ Wv,
              uint32_t* __restrict__ Q, uint32_t* __restrict__ Ko, uint32_t* __restrict__ V)
{
    extern __shared__ GemmSmemH smg[];
    int sel = blockIdx.x / 3;
    int bn  = (blockIdx.x % 3) * 128;
    const uint32_t* B = (sel == 0) ? Wq : (sel == 1) ? Wk : Wv;
    uint32_t*       C = (sel == 0) ? Q  : (sel == 1) ? Ko : V;
    gemm_core<false, false, 1>(smg, A, B, nullptr, nullptr, C,
                               MM, CC, CC, blockIdx.y * 128, bn);
}

// ---------------------------------------------------------------------------
// Small-M-tile FP16 GEMM for N=384 projections (Wo, W2): 64x128 tile,
// 4 warps of 32x64, 2-stage cp.async, 4 CTAs/SM. bias+residual, f32 out.
// (proven round-12 version)
// ---------------------------------------------------------------------------
struct GemmSmemH64 {
    uint32_t As[2][64][20];    // 10240 B
    uint32_t Bs[2][128][20];   // 20480 B
};
#define SMEM_GEMMH64 ((int)sizeof(GemmSmemH64))   // 30720 bytes

__global__ __launch_bounds__(128, 4)
void tgemm64(const uint32_t* __restrict__ A, const uint32_t* __restrict__ B,
             const float* __restrict__ bias, const float* __restrict__ res,
             float* __restrict__ C, int M, int N, int K)
{
    extern __shared__ GemmSmemH64 sm64[];
    GemmSmemH64* sm = sm64;

    const int Kp   = K >> 1;
    const int bm = blockIdx.y * 64;
    const int bn = blockIdx.x * 128;
    const int tid  = threadIdx.x;
    const int lane = tid & 31;
    const int wid  = tid >> 5;
    const int wm = (wid & 1) * 32;
    const int wn = (wid >> 1) * 64;
    const int grp = lane >> 2;
    const int tg  = lane & 3;

    float acc[2][8][4];
#pragma unroll
    for (int mt = 0; mt < 2; mt++)
#pragma unroll
        for (int nt = 0; nt < 8; nt++)
#pragma unroll
            for (int e = 0; e < 4; e++) acc[mt][nt][e] = 0.f;

    auto issue = [&](int s, int k0p) {
#pragma unroll
        for (int p = 0; p < 2; p++) {
            int i  = tid + p*128;
            int r  = i >> 2;
            int c4 = (i & 3) * 4;
            cp_async16(&sm->As[s][r][c4], A + (size_t)(bm + r)*Kp + k0p + c4);
        }
#pragma unroll
        for (int p = 0; p < 4; p++) {
            int i  = tid + p*128;
            int r  = i >> 2;
            int c4 = (i & 3) * 4;
            cp_async16(&sm->Bs[s][r][c4], B + (size_t)(bn + r)*Kp + k0p + c4);
        }
        CP_COMMIT();
    };

    const int nIter = K >> 5;
    issue(0, 0);

    for (int it = 0; it < nIter; it++) {
        const int cur = it & 1;
        CP_WAIT0();
        __syncthreads();
        if (it + 1 < nIter) issue(cur ^ 1, (it + 1) << 4);

#pragma unroll
        for (int kps = 0; kps < 16; kps += 8) {
            uint32_t af[2][4], bf[8][2];
#pragma unroll
            for (int mt = 0; mt < 2; mt++) {
                int r = wm + mt*16 + grp;
                af[mt][0] = sm->As[cur][r    ][kps + tg    ];
                af[mt][1] = sm->As[cur][r + 8][kps + tg    ];
                af[mt][2] = sm->As[cur][r    ][kps + tg + 4];
                af[mt][3] = sm->As[cur][r + 8][kps + tg + 4];
            }
#pragma unroll
            for (int nt = 0; nt < 8; nt++) {
                int c = wn + nt*8 + grp;
                bf[nt][0] = sm->Bs[cur][c][kps + tg    ];
                bf[nt][1] = sm->Bs[cur][c][kps + tg + 4];
            }
#pragma unroll
            for (int mt = 0; mt < 2; mt++)
#pragma unroll
                for (int nt = 0; nt < 8; nt++)
                    mma_f16(acc[mt][nt], af[mt], bf[nt]);
        }
    }

#pragma unroll
    for (int mt = 0; mt < 2; mt++) {
        int r0 = bm + wm + mt*16 + grp;
        int r1 = r0 + 8;
#pragma unroll
        for (int nt = 0; nt < 8; nt++) {
            int c = bn + wn + nt*8 + tg*2;
            float bv0 = bias[c], bv1 = bias[c+1];
            float2 ra = *(const float2*)(res + (size_t)r0*N + c);
            float2 rb = *(const float2*)(res + (size_t)r1*N + c);
            float2 w0 = {acc[mt][nt][0] + bv0 + ra.x, acc[mt][nt][1] + bv1 + ra.y};
            float2 w1 = {acc[mt][nt][2] + bv0 + rb.x, acc[mt][nt][3] + bv1 + rb.y};
            *(float2*)(C + (size_t)r0*N + c) = w0;
            *(float2*)(C + (size_t)r1*N + c) = w1;
        }
    }
}

// ---------------------------------------------------------------------------
// Tensor-core flash attention; q/k/v tf32, att output fp16. (unchanged)
// ---------------------------------------------------------------------------
#define AKS 68
#define AVS 72
#define APS 36
#define ATT_SMEM ((TT*AKS + TT*AVS + 8*32*APS) * (int)sizeof(uint32_t))

__global__ __launch_bounds__(256, 1)
void attn_mma(const uint32_t* __restrict__ Q, const uint32_t* __restrict__ K,
              const uint32_t* __restrict__ V, uint32_t* __restrict__ O)
{
    extern __shared__ uint32_t sm[];
    uint32_t* Ks = sm;
    uint32_t* Vs = sm + TT*AKS;
    uint32_t* Pb = sm + TT*AKS + TT*AVS;

    const int bh = blockIdx.x;
    const int b  = bh / NH;
    const int h  = bh % NH;
    const float scale = 0.05103103630798288f;  // 1/sqrt(384)

    const int tid = threadIdx.x;
    const uint32_t* kbase = K + (size_t)b*TT*CC + h*HD;
    const uint32_t* vbase = V + (size_t)b*TT*CC + h*HD;

    for (int i = tid; i < TT*16; i += 256) {
        int t  = i >> 4;
        int d4 = (i & 15) * 4;
        *(uint4*)&Ks[t*AKS + d4] = *(const uint4*)(kbase + (size_t)t*CC + d4);
        *(uint4*)&Vs[t*AVS + d4] = *(const uint4*)(vbase + (size_t)t*CC + d4);
    }
    __syncthreads();

    const int lane = tid & 31;
    const int w    = tid >> 5;
    const int grp  = lane >> 2;
    const int tg   = lane & 3;
    const int q0   = w * 32;

    const uint32_t* qbase = Q + (size_t)b*TT*CC + h*HD;
    uint32_t qa[2][8][4];
#pragma unroll
    for (int mt = 0; mt < 2; mt++) {
        int ra = q0 + mt*16 + grp;
        int rb = ra + 8;
#pragma unroll
        for (int ks = 0; ks < 8; ks++) {
            int d = ks*8 + tg;
            qa[mt][ks][0] = qbase[(size_t)ra*CC + d    ];
            qa[mt][ks][1] = qbase[(size_t)rb*CC + d    ];
            qa[mt][ks][2] = qbase[(size_t)ra*CC + d + 4];
            qa[mt][ks][3] = qbase[(size_t)rb*CC + d + 4];
        }
    }

    float o[2][8][4];
#pragma unroll
    for (int mt = 0; mt < 2; mt++)
#pragma unroll
        for (int nt = 0; nt < 8; nt++)
#pragma unroll
            for (int e = 0; e < 4; e++) o[mt][nt][e] = 0.f;

    float mrow[2][2] = {{-1e30f,-1e30f},{-1e30f,-1e30f}};
    float lrow[2][2] = {{0.f,0.f},{0.f,0.f}};

    uint32_t* myP = Pb + w * 32 * APS;

    for (int j = 0; j <= w; j++) {
        const int kbeg = j * 32;
        float s[2][4][4];
#pragma unroll
        for (int mt = 0; mt < 2; mt++)
#pragma unroll
            for (int nt = 0; nt < 4; nt++)
#pragma unroll
                for (int e = 0; e < 4; e++) s[mt][nt][e] = 0.f;

#pragma unroll
        for (int ks = 0; ks < 8; ks++) {
            uint32_t bf[4][2];
#pragma unroll
            for (int nt = 0; nt < 4; nt++) {
                int key = kbeg + nt*8 + grp;
                int d   = ks*8 + tg;
                bf[nt][0] = Ks[key*AKS + d    ];
                bf[nt][1] = Ks[key*AKS + d + 4];
            }
#pragma unroll
            for (int mt = 0; mt < 2; mt++)
#pragma unroll
                for (int nt = 0; nt < 4; nt++)
                    mma_tf32(s[mt][nt], qa[mt][ks], bf[nt]);
        }

#pragma unroll
        for (int mt = 0; mt < 2; mt++) {
            int ra = q0 + mt*16 + grp;
            int rb = ra + 8;
            float rmax0 = -1e30f, rmax1 = -1e30f;
#pragma unroll
            for (int nt = 0; nt < 4; nt++) {
                int c0 = kbeg + nt*8 + 2*tg;
#pragma unroll
                for (int e = 0; e < 4; e++) {
                    float vv = s[mt][nt][e] * scale;
                    int col = c0 + (e & 1);
                    int row = (e < 2) ? ra : rb;
                    if (j == w && col > row) vv = -1e30f;
                    s[mt][nt][e] = vv;
                }
                rmax0 = fmaxf(rmax0, fmaxf(s[mt][nt][0], s[mt][nt][1]));
                rmax1 = fmaxf(rmax1, fmaxf(s[mt][nt][2], s[mt][nt][3]));
            }
            rmax0 = fmaxf(rmax0, __shfl_xor_sync(0xFFFFFFFFu, rmax0, 1));
            rmax0 = fmaxf(rmax0, __shfl_xor_sync(0xFFFFFFFFu, rmax0, 2));
            rmax1 = fmaxf(rmax1, __shfl_xor_sync(0xFFFFFFFFu, rmax1, 1));
            rmax1 = fmaxf(rmax1, __shfl_xor_sync(0xFFFFFFFFu, rmax1, 2));

            float mn0 = fmaxf(mrow[mt][0], rmax0);
            float mn1 = fmaxf(mrow[mt][1], rmax1);
            float cr0 = __expf(mrow[mt][0] - mn0);
            float cr1 = __expf(mrow[mt][1] - mn1);
            mrow[mt][0] = mn0; mrow[mt][1] = mn1;

            float rs0 = 0.f, rs1 = 0.f;
#pragma unroll
            for (int nt = 0; nt < 4; nt++) {
                float p0 = __expf(s[mt][nt][0] - mn0);
                float p1 = __expf(s[mt][nt][1] - mn0);
                float p2 = __expf(s[mt][nt][2] - mn1);
                float p3 = __expf(s[mt][nt][3] - mn1);
                rs0 += p0 + p1; rs1 += p2 + p3;
                int cb = nt*8 + 2*tg;
                myP[(mt*16 + grp    )*APS + cb    ] = f2tf(p0);
                myP[(mt*16 + grp    )*APS + cb + 1] = f2tf(p1);
                myP[(mt*16 + grp + 8)*APS + cb    ] = f2tf(p2);
                myP[(mt*16 + grp + 8)*APS + cb + 1] = f2tf(p3);
            }
            rs0 += __shfl_xor_sync(0xFFFFFFFFu, rs0, 1);
            rs0 += __shfl_xor_sync(0xFFFFFFFFu, rs0, 2);
            rs1 += __shfl_xor_sync(0xFFFFFFFFu, rs1, 1);
            rs1 += __shfl_xor_sync(0xFFFFFFFFu, rs1, 2);
            lrow[mt][0] = lrow[mt][0]*cr0 + rs0;
            lrow[mt][1] = lrow[mt][1]*cr1 + rs1;
#pragma unroll
            for (int nt = 0; nt < 8; nt++) {
                o[mt][nt][0] *= cr0; o[mt][nt][1] *= cr0;
                o[mt][nt][2] *= cr1; o[mt][nt][3] *= cr1;
            }
        }
        __syncwarp();

#pragma unroll
        for (int ks2 = 0; ks2 < 4; ks2++) {
            uint32_t vb[8][2];
#pragma unroll
            for (int nt = 0; nt < 8; nt++) {
                int key = kbeg + ks2*8 + tg;
                int d   = nt*8 + grp;
                vb[nt][0] = Vs[ key     *AVS + d];
                vb[nt][1] = Vs[(key + 4)*AVS + d];
            }
#pragma unroll
            for (int mt = 0; mt < 2; mt++) {
                uint32_t pa[4];
                pa[0] = myP[(mt*16 + grp    )*APS + ks2*8 + tg    ];
                pa[1] = myP[(mt*16 + grp + 8)*APS + ks2*8 + tg    ];
                pa[2] = myP[(mt*16 + grp    )*APS + ks2*8 + tg + 4];
                pa[3] = myP[(mt*16 + grp + 8)*APS + ks2*8 + tg + 4];
#pragma unroll
                for (int nt = 0; nt < 8; nt++)
                    mma_tf32(o[mt][nt], pa, vb[nt]);
            }
        }
        __syncwarp();
    }

    // Epilogue: att output fp16 packed [row][kp], Kp = CC/2 = 192.
    uint32_t* obase = O + (size_t)b*TT*(CC/2) + h*(HD/2);
#pragma unroll
    for (int mt = 0; mt < 2; mt++) {
        int ra = q0 + mt*16 + grp;
        int rb = ra + 8;
        float inv0 = 1.f / lrow[mt][0];
        float inv1 = 1.f / lrow[mt][1];
#pragma unroll
        for (int nt = 0; nt < 8; nt++) {
            int dp = nt*4 + tg;
            obase[(size_t)ra*(CC/2) + dp] = packh2(o[mt][nt][0]*inv0, o[mt][nt][1]*inv0);
            obase[(size_t)rb*(CC/2) + dp] = packh2(o[mt][nt][2]*inv1, o[mt][nt][3]*inv1);
        }
    }
}

// ---------------------------------------------------------------------------
// Host
// ---------------------------------------------------------------------------
extern "C" void kernel_launch(void* const* d_in, const int* in_sizes, int n_in,
                              void* d_out, int out_size)
{
    (void)in_sizes; (void)n_in; (void)out_size;

    const int*   idx     = (const int*)  d_in[0];
    const float* tok_emb = (const float*)d_in[1];
    const float* pos_emb = (const float*)d_in[2];
    const float* ln1_g   = (const float*)d_in[3];
    const float* ln1_b   = (const float*)d_in[4];
    const float* wq      = (const float*)d_in[5];
    const float* wk      = (const float*)d_in[6];
    const float* wv      = (const float*)d_in[7];
    const float* wo      = (const float*)d_in[8];
    const float* wo_b    = (const float*)d_in[9];
    const float* ln2_g   = (const float*)d_in[10];
    const float* ln2_b   = (const float*)d_in[11];
    const float* w1      = (const float*)d_in[12];
    const float* b1      = (const float*)d_in[13];
    const float* w2      = (const float*)d_in[14];
    const float* b2      = (const float*)d_in[15];
    const float* lnf_g   = (const float*)d_in[16];
    const float* lnf_b   = (const float*)d_in[17];
    const float* lm_w    = (const float*)d_in[18];
    const float* lm_b    = (const float*)d_in[19];
    float* out = (float*)d_out;

    float *x;
    uint32_t *h, *q, *k, *v, *att, *u, *wt;
    cudaGetSymbolAddress((void**)&x,   g_x);
    cudaGetSymbolAddress((void**)&h,   g_h);
    cudaGetSymbolAddress((void**)&q,   g_q);
    cudaGetSymbolAddress((void**)&k,   g_k);
    cudaGetSymbolAddress((void**)&v,   g_v);
    cudaGetSymbolAddress((void**)&att, g_att);
    cudaGetSymbolAddress((void**)&u,   g_u);
    cudaGetSymbolAddress((void**)&wt,  g_wt);

    cudaFuncSetAttribute(attn_mma, cudaFuncAttributeMaxDynamicSharedMemorySize, ATT_SMEM);
    cudaFuncSetAttribute(tgemm<false,false,0>, cudaFuncAttributeMaxDynamicSharedMemorySize, SMEM_GEMMH);
    cudaFuncSetAttribute(tgemm<true ,false,2>, cudaFuncAttributeMaxDynamicSharedMemorySize, SMEM_GEMMH);
    cudaFuncSetAttribute(qkv_gemm,             cudaFuncAttributeMaxDynamicSharedMemorySize, SMEM_GEMMH);
    cudaFuncSetAttribute(tgemm64,              cudaFuncAttributeMaxDynamicSharedMemorySize, SMEM_GEMMH64);

    // Pre-convert + transpose all weights to fp16 [N][Kp] (single launch)
    cvt_trans_kernel<<<(R6 + 255)/256, 256>>>(wq, wk, wv, wo, w1, w2, lm_w, wt);

    {
        int total = MM * (CC/4);
        embed_kernel<<<(total + 255)/256, 256>>>(idx, tok_emb, pos_emb, x);
    }

    for (int L = 0; L < LL; L++) {
        const float* g1  = ln1_g + (size_t)L*CC;
        const float* bg1 = ln1_b + (size_t)L*CC;
        const uint32_t* Wq = wt + OFF16_WQ + (size_t)L*(CC*CC/2);
        const uint32_t* Wk = wt + OFF16_WK + (size_t)L*(CC*CC/2);
        const uint32_t* Wv = wt + OFF16_WV + (size_t)L*(CC*CC/2);
        const uint32_t* Wo = wt + OFF16_WO + (size_t)L*(CC*CC/2);
        const float* Wob = wo_b + (size_t)L*CC;
        const float* g2  = ln2_g + (size_t)L*CC;
        const float* bg2 = ln2_b + (size_t)L*CC;
        const uint32_t* W1 = wt + OFF16_W1 + (size_t)L*(CC*FF/2);
        const float* B1  = b1 + (size_t)L*FF;
        const uint32_t* W2 = wt + OFF16_W2 + (size_t)L*(FF*CC/2);
        const float* B2  = b2 + (size_t)L*CC;

        ln_kernel<<<MM/8, 256>>>(x, g1, bg1, h);
        qkv_gemm<<<dim3(9, 64), 256, SMEM_GEMMH>>>(h, Wq, Wk, Wv, q, k, v);
        attn_mma<<<BB*NH, 256, ATT_SMEM>>>(q, k, v, att);
        // x += att @ Wo + wo_b
        tgemm64<<<dim3(CC/128, MM/64), 128, SMEM_GEMMH64>>>(
            att, Wo, Wob, x, x, MM, CC, CC);
        ln_kernel<<<MM/8, 256>>>(x, g2, bg2, h);
        // u = relu(h @ W1 + b1), fp16 out
        tgemm<true,false,2><<<dim3(FF/128, MM/128), 256, SMEM_GEMMH>>>(
            h, W1, B1, nullptr, u, MM, FF, CC);
        // x += u @ W2 + b2
        tgemm64<<<dim3(CC/128, MM/64), 128, SMEM_GEMMH64>>>(
            u, W2, B2, x, x, MM, CC, FF);
    }

    ln_kernel<<<MM/8, 256>>>(x, lnf_g, lnf_b, h);
    // logits = h @ lm_w + lm_b
    tgemm<false,false,0><<<dim3(VV/128, MM/128), 256, SMEM_GEMMH>>>(
        h, wt + OFF16_LM, lm_b, nullptr, out, MM, VV, CC);
}

// round 15
// speedup vs baseline: 1.0154x; 1.0154x over previous
#include <cuda_runtime.h>
#include <cuda_fp16.h>
#include <math.h>
#include <stdint.h>

// Problem dims
#define BB 32
#define TT 256
#define CC 384
#define LL 6
#define NH 6
#define HD 64
#define VV 32000
#define MM (BB*TT)      // 8192
#define FF (4*CC)       // 1536

// fp16 weight scratch layout (uint32 = half2 units), stored TRANSPOSED [N][Kp]
#define OFF16_WQ 0
#define OFF16_WK 442368
#define OFF16_WV 884736
#define OFF16_WO 1327104
#define OFF16_W1 1769472
#define OFF16_W2 3538944
#define OFF16_LM 5308416
#define WT16_TOTAL 11452416

// Scratch (device globals; no allocations allowed)
__device__ float    g_x[MM*CC];          // residual stream (f32)
__device__ uint32_t g_h[MM*CC/2];        // LN output (fp16 packed, Kp=192)
__device__ uint32_t g_q[MM*CC];          // tf32 (attention input)
__device__ uint32_t g_k[MM*CC];
__device__ uint32_t g_v[MM*CC];
__device__ uint32_t g_att[MM*CC/2];      // fp16 packed
__device__ uint32_t g_u[MM*FF/2];        // fp16 packed
__device__ uint32_t g_wt[WT16_TOTAL];    // fp16 transposed weights

// ---------------------------------------------------------------------------
// Helpers
// ---------------------------------------------------------------------------
__device__ __forceinline__ uint32_t f2tf(float f) {
    uint32_t u;
    asm("cvt.rna.tf32.f32 %0, %1;" : "=r"(u) : "f"(f));
    return u;
}

__device__ __forceinline__ uint32_t packh2(float lo, float hi) {
    __half2 h = __floats2half2_rn(lo, hi);
    return *(uint32_t*)&h;
}

__device__ __forceinline__ void mma_tf32(float* c, const uint32_t* a, const uint32_t* b) {
    asm volatile(
        "mma.sync.aligned.m16n8k8.row.col.f32.tf32.tf32.f32 "
        "{%0,%1,%2,%3}, {%4,%5,%6,%7}, {%8,%9}, {%0,%1,%2,%3};"
        : "+f"(c[0]), "+f"(c[1]), "+f"(c[2]), "+f"(c[3])
        : "r"(a[0]), "r"(a[1]), "r"(a[2]), "r"(a[3]),
          "r"(b[0]), "r"(b[1]));
}

__device__ __forceinline__ void mma_f16(float* c, const uint32_t* a, const uint32_t* b) {
    asm volatile(
        "mma.sync.aligned.m16n8k16.row.col.f32.f16.f16.f32 "
        "{%0,%1,%2,%3}, {%4,%5,%6,%7}, {%8,%9}, {%0,%1,%2,%3};"
        : "+f"(c[0]), "+f"(c[1]), "+f"(c[2]), "+f"(c[3])
        : "r"(a[0]), "r"(a[1]), "r"(a[2]), "r"(a[3]),
          "r"(b[0]), "r"(b[1]));
}

__device__ __forceinline__ void cp_async16(void* sptr, const void* gptr) {
    uint32_t sa = (uint32_t)__cvta_generic_to_shared(sptr);
    asm volatile("cp.async.cg.shared.global [%0], [%1], 16;\n" :: "r"(sa), "l"(gptr));
}
#define CP_COMMIT() asm volatile("cp.async.commit_group;\n" ::: "memory")
#define CP_WAIT0()  asm volatile("cp.async.wait_group 0;\n" ::: "memory")

// ---------------------------------------------------------------------------
// Fused transpose + fp16 convert of ALL weights, one launch.
// ---------------------------------------------------------------------------
#define R0 110592
#define R1 221184
#define R2 331776
#define R3 442368
#define R4 884736
#define R5 1327104
#define R6 2863104

__global__ void cvt_trans_kernel(const float* __restrict__ wq, const float* __restrict__ wk,
                                 const float* __restrict__ wv, const float* __restrict__ wo,
                                 const float* __restrict__ w1, const float* __restrict__ w2,
                                 const float* __restrict__ lm, uint32_t* __restrict__ wt)
{
    int f = blockIdx.x * blockDim.x + threadIdx.x;
    if (f >= R6) return;
    const float* src; uint32_t* dst; int K, N, local;
    if (f < R0)      { src = wq; dst = wt + OFF16_WQ; K = CC; N = CC; local = f; }
    else if (f < R1) { src = wk; dst = wt + OFF16_WK; K = CC; N = CC; local = f - R0; }
    else if (f < R2) { src = wv; dst = wt + OFF16_WV; K = CC; N = CC; local = f - R1; }
    else if (f < R3) { src = wo; dst = wt + OFF16_WO; K = CC; N = CC; local = f - R2; }
    else if (f < R4) { src = w1; dst = wt + OFF16_W1; K = CC; N = FF; local = f - R3; }
    else if (f < R5) { src = w2; dst = wt + OFF16_W2; K = FF; N = CC; local = f - R4; }
    else             { src = lm; dst = wt + OFF16_LM; K = CC; N = VV; local = f - R5; }

    int Kp    = K >> 1;
    int PL    = (K >> 3) * N;
    int layer = local / PL;
    int r     = local - layer * PL;
    int kg    = r / N;
    int n     = r - kg * N;

    const float* s0 = src + (size_t)layer*K*N + (size_t)(kg*8)*N + n;
    float s[8];
#pragma unroll
    for (int t = 0; t < 8; t++) s[t] = s0[(size_t)t*N];
    uint32_t* d = dst + (size_t)layer*N*Kp + (size_t)n*Kp + kg*4;
    uint4 o;
    o.x = packh2(s[0], s[1]);
    o.y = packh2(s[2], s[3]);
    o.z = packh2(s[4], s[5]);
    o.w = packh2(s[6], s[7]);
    *(uint4*)d = o;
}

// ---------------------------------------------------------------------------
// Embedding (f32 residual stream)
// ---------------------------------------------------------------------------
__global__ void embed_kernel(const int* __restrict__ idx,
                             const float* __restrict__ tok,
                             const float* __restrict__ pos,
                             float* __restrict__ X)
{
    int i = blockIdx.x * blockDim.x + threadIdx.x;
    if (i >= MM * (CC/4)) return;
    int row = i / (CC/4);
    int c4  = i % (CC/4);
    int t   = idx[row];
    int p   = row & (TT-1);
    float4 a = *(const float4*)(tok + (size_t)t*CC + c4*4);
    float4 e = *(const float4*)(pos + (size_t)p*CC + c4*4);
    a.x += e.x; a.y += e.y; a.z += e.z; a.w += e.w;
    *(float4*)(X + (size_t)row*CC + c4*4) = a;
}

// ---------------------------------------------------------------------------
// LayerNorm: one warp per row; output fp16 packed.
// ---------------------------------------------------------------------------
__global__ void ln_kernel(const float* __restrict__ X,
                          const float* __restrict__ g,
                          const float* __restrict__ b,
                          uint32_t* __restrict__ Y)
{
    int row  = blockIdx.x * 8 + (threadIdx.x >> 5);
    int lane = threadIdx.x & 31;
    if (row >= MM) return;
    const float* x = X + (size_t)row*CC;
    float2 v[6];
    float s = 0.f, ss = 0.f;
#pragma unroll
    for (int j = 0; j < 6; j++) {
        int c = j*64 + 2*lane;
        v[j] = *(const float2*)(x + c);
        s  += v[j].x + v[j].y;
        ss += v[j].x*v[j].x + v[j].y*v[j].y;
    }
#pragma unroll
    for (int o = 16; o; o >>= 1) {
        s  += __shfl_xor_sync(0xFFFFFFFFu, s,  o);
        ss += __shfl_xor_sync(0xFFFFFFFFu, ss, o);
    }
    float mean = s  * (1.0f/CC);
    float var  = ss * (1.0f/CC) - mean*mean;
    float inv  = rsqrtf(var + 1e-5f);
    uint32_t* y = Y + (size_t)row*(CC/2);
#pragma unroll
    for (int j = 0; j < 6; j++) {
        int c = j*64 + 2*lane;
        float a0 = (v[j].x - mean)*inv*g[c    ] + b[c    ];
        float a1 = (v[j].y - mean)*inv*g[c + 1] + b[c + 1];
        y[j*32 + lane] = packh2(a0, a1);
    }
}

// ---------------------------------------------------------------------------
// Unified FP16 GEMM core: 64x128 CTA tile, BK=32 (16 kp), 128 threads,
// 4 warps of 32x64, 2-stage cp.async, 30 KB smem -> 4 CTAs/SM (16 warps/SM,
// DECOUPLED barriers across 4 CTAs). Proven best per-FLOP engine (tgemm64).
// OUTMODE: 0 = f32, 1 = tf32, 2 = fp16 packed.
// ---------------------------------------------------------------------------
struct GemmSmem64 {
    uint32_t As[2][64][20];    // 10240 B
    uint32_t Bs[2][128][20];   // 20480 B
};
#define SMEM_GEMM64 ((int)sizeof(GemmSmem64))   // 30720 bytes

template<bool RELU, bool RES, int OUTMODE>
__device__ __forceinline__
void gemm64_core(GemmSmem64* sm,
                 const uint32_t* __restrict__ A, const uint32_t* __restrict__ B,
                 const float* __restrict__ bias, const float* __restrict__ res,
                 void* __restrict__ Cv, int M, int N, int K, int bm, int bn)
{
    const int Kp   = K >> 1;
    const int tid  = threadIdx.x;
    const int lane = tid & 31;
    const int wid  = tid >> 5;
    const int wm = (wid & 1) * 32;
    const int wn = (wid >> 1) * 64;
    const int grp = lane >> 2;
    const int tg  = lane & 3;

    float acc[2][8][4];
#pragma unroll
    for (int mt = 0; mt < 2; mt++)
#pragma unroll
        for (int nt = 0; nt < 8; nt++)
#pragma unroll
            for (int e = 0; e < 4; e++) acc[mt][nt][e] = 0.f;

    auto issue = [&](int s, int k0p) {
#pragma unroll
        for (int p = 0; p < 2; p++) {          // A: 64 rows x 16 uints = 256 chunks
            int i  = tid + p*128;
            int r  = i >> 2;
            int c4 = (i & 3) * 4;
            cp_async16(&sm->As[s][r][c4], A + (size_t)(bm + r)*Kp + k0p + c4);
        }
#pragma unroll
        for (int p = 0; p < 4; p++) {          // B: 128 n x 16 uints = 512 chunks
            int i  = tid + p*128;
            int r  = i >> 2;
            int c4 = (i & 3) * 4;
            cp_async16(&sm->Bs[s][r][c4], B + (size_t)(bn + r)*Kp + k0p + c4);
        }
        CP_COMMIT();
    };

    const int nIter = K >> 5;
    issue(0, 0);

    for (int it = 0; it < nIter; it++) {
        const int cur = it & 1;
        CP_WAIT0();
        __syncthreads();
        if (it + 1 < nIter) issue(cur ^ 1, (it + 1) << 4);

#pragma unroll
        for (int kps = 0; kps < 16; kps += 8) {
            uint32_t af[2][4], bf[8][2];
#pragma unroll
            for (int mt = 0; mt < 2; mt++) {
                int r = wm + mt*16 + grp;
                af[mt][0] = sm->As[cur][r    ][kps + tg    ];
                af[mt][1] = sm->As[cur][r + 8][kps + tg    ];
                af[mt][2] = sm->As[cur][r    ][kps + tg + 4];
                af[mt][3] = sm->As[cur][r + 8][kps + tg + 4];
            }
#pragma unroll
            for (int nt = 0; nt < 8; nt++) {
                int c = wn + nt*8 + grp;
                bf[nt][0] = sm->Bs[cur][c][kps + tg    ];
                bf[nt][1] = sm->Bs[cur][c][kps + tg + 4];
            }
#pragma unroll
            for (int mt = 0; mt < 2; mt++)
#pragma unroll
                for (int nt = 0; nt < 8; nt++)
                    mma_f16(acc[mt][nt], af[mt], bf[nt]);
        }
    }

    // Epilogue
#pragma unroll
    for (int mt = 0; mt < 2; mt++) {
        int r0 = bm + wm + mt*16 + grp;
        int r1 = r0 + 8;
#pragma unroll
        for (int nt = 0; nt < 8; nt++) {
            int c = bn + wn + nt*8 + tg*2;
            float o0x = acc[mt][nt][0], o0y = acc[mt][nt][1];
            float o1x = acc[mt][nt][2], o1y = acc[mt][nt][3];
            if (bias) {
                float bv0 = bias[c], bv1 = bias[c+1];
                o0x += bv0; o0y += bv1; o1x += bv0; o1y += bv1;
            }
            if (RES) {
                float2 ra = *(const float2*)(res + (size_t)r0*N + c);
                float2 rb = *(const float2*)(res + (size_t)r1*N + c);
                o0x += ra.x; o0y += ra.y; o1x += rb.x; o1y += rb.y;
            }
            if (RELU) {
                o0x = fmaxf(o0x, 0.f); o0y = fmaxf(o0y, 0.f);
                o1x = fmaxf(o1x, 0.f); o1y = fmaxf(o1y, 0.f);
            }
            if (OUTMODE == 0) {
                float* C = (float*)Cv;
                float2 w0 = {o0x, o0y};
                float2 w1 = {o1x, o1y};
                *(float2*)(C + (size_t)r0*N + c) = w0;
                *(float2*)(C + (size_t)r1*N + c) = w1;
            } else if (OUTMODE == 1) {
                uint32_t* C = (uint32_t*)Cv;
                uint2 w0 = {f2tf(o0x), f2tf(o0y)};
                uint2 w1 = {f2tf(o1x), f2tf(o1y)};
                *(uint2*)(C + (size_t)r0*N + c) = w0;
                *(uint2*)(C + (size_t)r1*N + c) = w1;
            } else {
                uint32_t* C = (uint32_t*)Cv;
                C[(size_t)r0*(N>>1) + (c>>1)] = packh2(o0x, o0y);
                C[(size_t)r1*(N>>1) + (c>>1)] = packh2(o1x, o1y);
            }
        }
    }
}

template<bool RELU, bool RES, int OUTMODE>
__global__ __launch_bounds__(128, 4)
void tgemm64k(const uint32_t* __restrict__ A, const uint32_t* __restrict__ B,
              const float* __restrict__ bias, const float* __restrict__ res,
              void* __restrict__ C, int M, int N, int K)
{
    extern __shared__ GemmSmem64 sm64[];
    gemm64_core<RELU, RES, OUTMODE>(sm64, A, B, bias, res, C, M, N, K,
                                    blockIdx.y * 64, blockIdx.x * 128);
}

// Fused QKV: grid.x = 9 (3 matrices x 3 col-tiles of 128), grid.y = 128. tf32 out.
__global__ __launch_bounds__(128, 4)
void qkv_gemm(const uint32_t* __restrict__ A,
              const uint32_t* __restrict__ Wq, const uint32_t* __restrict__ Wk,
              const uint32_t* __restrict__ Wv,
              uint32_t* __restrict__ Q, uint32_t* __restrict__ Ko, uint32_t* __restrict__ V)
{
    extern __shared__ GemmSmem64 sm64[];
    int sel = blockIdx.x / 3;
    int bn  = (blockIdx.x % 3) * 128;
    const uint32_t* B = (sel == 0) ? Wq : (sel == 1) ? Wk : Wv;
    uint32_t*       C = (sel == 0) ? Q  : (sel == 1) ? Ko : V;
    gemm64_core<false, false, 1>(sm64, A, B, nullptr, nullptr, C,
                                 MM, CC, CC, blockIdx.y * 64, bn);
}

// ---------------------------------------------------------------------------
// Tensor-core flash attention; q/k/v tf32, att output fp16. (unchanged)
// ---------------------------------------------------------------------------
#define AKS 68
#define AVS 72
#define APS 36
#define ATT_SMEM ((TT*AKS + TT*AVS + 8*32*APS) * (int)sizeof(uint32_t))

__global__ __launch_bounds__(256, 1)
void attn_mma(const uint32_t* __restrict__ Q, const uint32_t* __restrict__ K,
              const uint32_t* __restrict__ V, uint32_t* __restrict__ O)
{
    extern __shared__ uint32_t sm[];
    uint32_t* Ks = sm;
    uint32_t* Vs = sm + TT*AKS;
    uint32_t* Pb = sm + TT*AKS + TT*AVS;

    const int bh = blockIdx.x;
    const int b  = bh / NH;
    const int h  = bh % NH;
    const float scale = 0.05103103630798288f;  // 1/sqrt(384)

    const int tid = threadIdx.x;
    const uint32_t* kbase = K + (size_t)b*TT*CC + h*HD;
    const uint32_t* vbase = V + (size_t)b*TT*CC + h*HD;

    for (int i = tid; i < TT*16; i += 256) {
        int t  = i >> 4;
        int d4 = (i & 15) * 4;
        *(uint4*)&Ks[t*AKS + d4] = *(const uint4*)(kbase + (size_t)t*CC + d4);
        *(uint4*)&Vs[t*AVS + d4] = *(const uint4*)(vbase + (size_t)t*CC + d4);
    }
    __syncthreads();

    const int lane = tid & 31;
    const int w    = tid >> 5;
    const int grp  = lane >> 2;
    const int tg   = lane & 3;
    const int q0   = w * 32;

    const uint32_t* qbase = Q + (size_t)b*TT*CC + h*HD;
    uint32_t qa[2][8][4];
#pragma unroll
    for (int mt = 0; mt < 2; mt++) {
        int ra = q0 + mt*16 + grp;
        int rb = ra + 8;
#pragma unroll
        for (int ks = 0; ks < 8; ks++) {
            int d = ks*8 + tg;
            qa[mt][ks][0] = qbase[(size_t)ra*CC + d    ];
            qa[mt][ks][1] = qbase[(size_t)rb*CC + d    ];
            qa[mt][ks][2] = qbase[(size_t)ra*CC + d + 4];
            qa[mt][ks][3] = qbase[(size_t)rb*CC + d + 4];
        }
    }

    float o[2][8][4];
#pragma unroll
    for (int mt = 0; mt < 2; mt++)
#pragma unroll
        for (int nt = 0; nt < 8; nt++)
#pragma unroll
            for (int e = 0; e < 4; e++) o[mt][nt][e] = 0.f;

    float mrow[2][2] = {{-1e30f,-1e30f},{-1e30f,-1e30f}};
    float lrow[2][2] = {{0.f,0.f},{0.f,0.f}};

    uint32_t* myP = Pb + w * 32 * APS;

    for (int j = 0; j <= w; j++) {
        const int kbeg = j * 32;
        float s[2][4][4];
#pragma unroll
        for (int mt = 0; mt < 2; mt++)
#pragma unroll
            for (int nt = 0; nt < 4; nt++)
#pragma unroll
                for (int e = 0; e < 4; e++) s[mt][nt][e] = 0.f;

#pragma unroll
        for (int ks = 0; ks < 8; ks++) {
            uint32_t bf[4][2];
#pragma unroll
            for (int nt = 0; nt < 4; nt++) {
                int key = kbeg + nt*8 + grp;
                int d   = ks*8 + tg;
                bf[nt][0] = Ks[key*AKS + d    ];
                bf[nt][1] = Ks[key*AKS + d + 4];
            }
#pragma unroll
            for (int mt = 0; mt < 2; mt++)
#pragma unroll
                for (int nt = 0; nt < 4; nt++)
                    mma_tf32(s[mt][nt], qa[mt][ks], bf[nt]);
        }

#pragma unroll
        for (int mt = 0; mt < 2; mt++) {
            int ra = q0 + mt*16 + grp;
            int rb = ra + 8;
            float rmax0 = -1e30f, rmax1 = -1e30f;
#pragma unroll
            for (int nt = 0; nt < 4; nt++) {
                int c0 = kbeg + nt*8 + 2*tg;
#pragma unroll
                for (int e = 0; e < 4; e++) {
                    float vv = s[mt][nt][e] * scale;
                    int col = c0 + (e & 1);
                    int row = (e < 2) ? ra : rb;
                    if (j == w && col > row) vv = -1e30f;
                    s[mt][nt][e] = vv;
                }
                rmax0 = fmaxf(rmax0, fmaxf(s[mt][nt][0], s[mt][nt][1]));
                rmax1 = fmaxf(rmax1, fmaxf(s[mt][nt][2], s[mt][nt][3]));
            }
            rmax0 = fmaxf(rmax0, __shfl_xor_sync(0xFFFFFFFFu, rmax0, 1));
            rmax0 = fmaxf(rmax0, __shfl_xor_sync(0xFFFFFFFFu, rmax0, 2));
            rmax1 = fmaxf(rmax1, __shfl_xor_sync(0xFFFFFFFFu, rmax1, 1));
            rmax1 = fmaxf(rmax1, __shfl_xor_sync(0xFFFFFFFFu, rmax1, 2));

            float mn0 = fmaxf(mrow[mt][0], rmax0);
            float mn1 = fmaxf(mrow[mt][1], rmax1);
            float cr0 = __expf(mrow[mt][0] - mn0);
            float cr1 = __expf(mrow[mt][1] - mn1);
            mrow[mt][0] = mn0; mrow[mt][1] = mn1;

            float rs0 = 0.f, rs1 = 0.f;
#pragma unroll
            for (int nt = 0; nt < 4; nt++) {
                float p0 = __expf(s[mt][nt][0] - mn0);
                float p1 = __expf(s[mt][nt][1] - mn0);
                float p2 = __expf(s[mt][nt][2] - mn1);
                float p3 = __expf(s[mt][nt][3] - mn1);
                rs0 += p0 + p1; rs1 += p2 + p3;
                int cb = nt*8 + 2*tg;
                myP[(mt*16 + grp    )*APS + cb    ] = f2tf(p0);
                myP[(mt*16 + grp    )*APS + cb + 1] = f2tf(p1);
                myP[(mt*16 + grp + 8)*APS + cb    ] = f2tf(p2);
                myP[(mt*16 + grp + 8)*APS + cb + 1] = f2tf(p3);
            }
            rs0 += __shfl_xor_sync(0xFFFFFFFFu, rs0, 1);
            rs0 += __shfl_xor_sync(0xFFFFFFFFu, rs0, 2);
            rs1 += __shfl_xor_sync(0xFFFFFFFFu, rs1, 1);
            rs1 += __shfl_xor_sync(0xFFFFFFFFu, rs1, 2);
            lrow[mt][0] = lrow[mt][0]*cr0 + rs0;
            lrow[mt][1] = lrow[mt][1]*cr1 + rs1;
#pragma unroll
            for (int nt = 0; nt < 8; nt++) {
                o[mt][nt][0] *= cr0; o[mt][nt][1] *= cr0;
                o[mt][nt][2] *= cr1; o[mt][nt][3] *= cr1;
            }
        }
        __syncwarp();

#pragma unroll
        for (int ks2 = 0; ks2 < 4; ks2++) {
            uint32_t vb[8][2];
#pragma unroll
            for (int nt = 0; nt < 8; nt++) {
                int key = kbeg + ks2*8 + tg;
                int d   = nt*8 + grp;
                vb[nt][0] = Vs[ key     *AVS + d];
                vb[nt][1] = Vs[(key + 4)*AVS + d];
            }
#pragma unroll
            for (int mt = 0; mt < 2; mt++) {
                uint32_t pa[4];
                pa[0] = myP[(mt*16 + grp    )*APS + ks2*8 + tg    ];
                pa[1] = myP[(mt*16 + grp + 8)*APS + ks2*8 + tg    ];
                pa[2] = myP[(mt*16 + grp    )*APS + ks2*8 + tg + 4];
                pa[3] = myP[(mt*16 + grp + 8)*APS + ks2*8 + tg + 4];
#pragma unroll
                for (int nt = 0; nt < 8; nt++)
                    mma_tf32(o[mt][nt], pa, vb[nt]);
            }
        }
        __syncwarp();
    }

    // Epilogue: att output fp16 packed [row][kp], Kp = CC/2 = 192.
    uint32_t* obase = O + (size_t)b*TT*(CC/2) + h*(HD/2);
#pragma unroll
    for (int mt = 0; mt < 2; mt++) {
        int ra = q0 + mt*16 + grp;
        int rb = ra + 8;
        float inv0 = 1.f / lrow[mt][0];
        float inv1 = 1.f / lrow[mt][1];
#pragma unroll
        for (int nt = 0; nt < 8; nt++) {
            int dp = nt*4 + tg;
            obase[(size_t)ra*(CC/2) + dp] = packh2(o[mt][nt][0]*inv0, o[mt][nt][1]*inv0);
            obase[(size_t)rb*(CC/2) + dp] = packh2(o[mt][nt][2]*inv1, o[mt][nt][3]*inv1);
        }
    }
}

// ---------------------------------------------------------------------------
// Host
// ---------------------------------------------------------------------------
extern "C" void kernel_launch(void* const* d_in, const int* in_sizes, int n_in,
                              void* d_out, int out_size)
{
    (void)in_sizes; (void)n_in; (void)out_size;

    const int*   idx     = (const int*)  d_in[0];
    const float* tok_emb = (const float*)d_in[1];
    const float* pos_emb = (const float*)d_in[2];
    const float* ln1_g   = (const float*)d_in[3];
    const float* ln1_b   = (const float*)d_in[4];
    const float* wq      = (const float*)d_in[5];
    const float* wk      = (const float*)d_in[6];
    const float* wv      = (const float*)d_in[7];
    const float* wo      = (const float*)d_in[8];
    const float* wo_b    = (const float*)d_in[9];
    const float* ln2_g   = (const float*)d_in[10];
    const float* ln2_b   = (const float*)d_in[11];
    const float* w1      = (const float*)d_in[12];
    const float* b1      = (const float*)d_in[13];
    const float* w2      = (const float*)d_in[14];
    const float* b2      = (const float*)d_in[15];
    const float* lnf_g   = (const float*)d_in[16];
    const float* lnf_b   = (const float*)d_in[17];
    const float* lm_w    = (const float*)d_in[18];
    const float* lm_b    = (const float*)d_in[19];
    float* out = (float*)d_out;

    float *x;
    uint32_t *h, *q, *k, *v, *att, *u, *wt;
    cudaGetSymbolAddress((void**)&x,   g_x);
    cudaGetSymbolAddress((void**)&h,   g_h);
    cudaGetSymbolAddress((void**)&q,   g_q);
    cudaGetSymbolAddress((void**)&k,   g_k);
    cudaGetSymbolAddress((void**)&v,   g_v);
    cudaGetSymbolAddress((void**)&att, g_att);
    cudaGetSymbolAddress((void**)&u,   g_u);
    cudaGetSymbolAddress((void**)&wt,  g_wt);

    cudaFuncSetAttribute(attn_mma, cudaFuncAttributeMaxDynamicSharedMemorySize, ATT_SMEM);
    cudaFuncSetAttribute(tgemm64k<false,false,0>, cudaFuncAttributeMaxDynamicSharedMemorySize, SMEM_GEMM64);
    cudaFuncSetAttribute(tgemm64k<false,true ,0>, cudaFuncAttributeMaxDynamicSharedMemorySize, SMEM_GEMM64);
    cudaFuncSetAttribute(tgemm64k<true ,false,2>, cudaFuncAttributeMaxDynamicSharedMemorySize, SMEM_GEMM64);
    cudaFuncSetAttribute(qkv_gemm,                cudaFuncAttributeMaxDynamicSharedMemorySize, SMEM_GEMM64);

    // Pre-convert + transpose all weights to fp16 [N][Kp] (single launch)
    cvt_trans_kernel<<<(R6 + 255)/256, 256>>>(wq, wk, wv, wo, w1, w2, lm_w, wt);

    {
        int total = MM * (CC/4);
        embed_kernel<<<(total + 255)/256, 256>>>(idx, tok_emb, pos_emb, x);
    }

    for (int L = 0; L < LL; L++) {
        const float* g1  = ln1_g + (size_t)L*CC;
        const float* bg1 = ln1_b + (size_t)L*CC;
        const uint32_t* Wq = wt + OFF16_WQ + (size_t)L*(CC*CC/2);
        const uint32_t* Wk = wt + OFF16_WK + (size_t)L*(CC*CC/2);
        const uint32_t* Wv = wt + OFF16_WV + (size_t)L*(CC*CC/2);
        const uint32_t* Wo = wt + OFF16_WO + (size_t)L*(CC*CC/2);
        const float* Wob = wo_b + (size_t)L*CC;
        const float* g2  = ln2_g + (size_t)L*CC;
        const float* bg2 = ln2_b + (size_t)L*CC;
        const uint32_t* W1 = wt + OFF16_W1 + (size_t)L*(CC*FF/2);
        const float* B1  = b1 + (size_t)L*FF;
        const uint32_t* W2 = wt + OFF16_W2 + (size_t)L*(FF*CC/2);
        const float* B2  = b2 + (size_t)L*CC;

        ln_kernel<<<MM/8, 256>>>(x, g1, bg1, h);
        qkv_gemm<<<dim3(9, MM/64), 128, SMEM_GEMM64>>>(h, Wq, Wk, Wv, q, k, v);
        attn_mma<<<BB*NH, 256, ATT_SMEM>>>(q, k, v, att);
        // x += att @ Wo + wo_b
        tgemm64k<false,true,0><<<dim3(CC/128, MM/64), 128, SMEM_GEMM64>>>(
            att, Wo, Wob, x, x, MM, CC, CC);
        ln_kernel<<<MM/8, 256>>>(x, g2, bg2, h);
        // u = relu(h @ W1 + b1), fp16 out
        tgemm64k<true,false,2><<<dim3(FF/128, MM/64), 128, SMEM_GEMM64>>>(
            h, W1, B1, nullptr, u, MM, FF, CC);
        // x += u @ W2 + b2
        tgemm64k<false,true,0><<<dim3(CC/128, MM/64), 128, SMEM_GEMM64>>>(
            u, W2, B2, x, x, MM, CC, FF);
    }

    ln_kernel<<<MM/8, 256>>>(x, lnf_g, lnf_b, h);
    // logits = h @ lm_w + lm_b
    tgemm64k<false,false,0><<<dim3(VV/128, MM/64), 128, SMEM_GEMM64>>>(
        h, wt + OFF16_LM, lm_b, nullptr, out, MM, VV, CC);
}

// round 16
// speedup vs baseline: 1.0186x; 1.0031x over previous
#include <cuda_runtime.h>
#include <cuda_fp16.h>
#include <math.h>
#include <stdint.h>

// Problem dims
#define BB 32
#define TT 256
#define CC 384
#define LL 6
#define NH 6
#define HD 64
#define VV 32000
#define MM (BB*TT)      // 8192
#define FF (4*CC)       // 1536

// fp16 weight scratch layout (uint32 = half2 units), stored TRANSPOSED [N][Kp]
#define OFF16_WQ 0
#define OFF16_WK 442368
#define OFF16_WV 884736
#define OFF16_WO 1327104
#define OFF16_W1 1769472
#define OFF16_W2 3538944
#define OFF16_LM 5308416
#define WT16_TOTAL 11452416

// Scratch (device globals; no allocations allowed)
__device__ float    g_x[MM*CC];          // residual stream (f32)
__device__ uint32_t g_h[MM*CC/2];        // LN output (fp16 packed, Kp=192)
__device__ uint32_t g_q[MM*CC];          // tf32 (attention input)
__device__ uint32_t g_k[MM*CC];
__device__ uint32_t g_v[MM*CC];
__device__ uint32_t g_att[MM*CC/2];      // fp16 packed
__device__ uint32_t g_u[MM*FF/2];        // fp16 packed
__device__ uint32_t g_wt[WT16_TOTAL];    // fp16 transposed weights

// ---------------------------------------------------------------------------
// Helpers
// ---------------------------------------------------------------------------
__device__ __forceinline__ uint32_t f2tf(float f) {
    uint32_t u;
    asm("cvt.rna.tf32.f32 %0, %1;" : "=r"(u) : "f"(f));
    return u;
}

__device__ __forceinline__ uint32_t packh2(float lo, float hi) {
    __half2 h = __floats2half2_rn(lo, hi);
    return *(uint32_t*)&h;
}

__device__ __forceinline__ void mma_tf32(float* c, const uint32_t* a, const uint32_t* b) {
    asm volatile(
        "mma.sync.aligned.m16n8k8.row.col.f32.tf32.tf32.f32 "
        "{%0,%1,%2,%3}, {%4,%5,%6,%7}, {%8,%9}, {%0,%1,%2,%3};"
        : "+f"(c[0]), "+f"(c[1]), "+f"(c[2]), "+f"(c[3])
        : "r"(a[0]), "r"(a[1]), "r"(a[2]), "r"(a[3]),
          "r"(b[0]), "r"(b[1]));
}

__device__ __forceinline__ void mma_f16(float* c, const uint32_t* a, const uint32_t* b) {
    asm volatile(
        "mma.sync.aligned.m16n8k16.row.col.f32.f16.f16.f32 "
        "{%0,%1,%2,%3}, {%4,%5,%6,%7}, {%8,%9}, {%0,%1,%2,%3};"
        : "+f"(c[0]), "+f"(c[1]), "+f"(c[2]), "+f"(c[3])
        : "r"(a[0]), "r"(a[1]), "r"(a[2]), "r"(a[3]),
          "r"(b[0]), "r"(b[1]));
}

__device__ __forceinline__ void cp_async16(void* sptr, const void* gptr) {
    uint32_t sa = (uint32_t)__cvta_generic_to_shared(sptr);
    asm volatile("cp.async.cg.shared.global [%0], [%1], 16;\n" :: "r"(sa), "l"(gptr));
}
#define CP_COMMIT() asm volatile("cp.async.commit_group;\n" ::: "memory")
#define CP_WAIT0()  asm volatile("cp.async.wait_group 0;\n" ::: "memory")

// ---------------------------------------------------------------------------
// Fused transpose + fp16 convert of ALL weights, one launch.
// ---------------------------------------------------------------------------
#define R0 110592
#define R1 221184
#define R2 331776
#define R3 442368
#define R4 884736
#define R5 1327104
#define R6 2863104

__global__ void cvt_trans_kernel(const float* __restrict__ wq, const float* __restrict__ wk,
                                 const float* __restrict__ wv, const float* __restrict__ wo,
                                 const float* __restrict__ w1, const float* __restrict__ w2,
                                 const float* __restrict__ lm, uint32_t* __restrict__ wt)
{
    int f = blockIdx.x * blockDim.x + threadIdx.x;
    if (f >= R6) return;
    const float* src; uint32_t* dst; int K, N, local;
    if (f < R0)      { src = wq; dst = wt + OFF16_WQ; K = CC; N = CC; local = f; }
    else if (f < R1) { src = wk; dst = wt + OFF16_WK; K = CC; N = CC; local = f - R0; }
    else if (f < R2) { src = wv; dst = wt + OFF16_WV; K = CC; N = CC; local = f - R1; }
    else if (f < R3) { src = wo; dst = wt + OFF16_WO; K = CC; N = CC; local = f - R2; }
    else if (f < R4) { src = w1; dst = wt + OFF16_W1; K = CC; N = FF; local = f - R3; }
    else if (f < R5) { src = w2; dst = wt + OFF16_W2; K = FF; N = CC; local = f - R4; }
    else             { src = lm; dst = wt + OFF16_LM; K = CC; N = VV; local = f - R5; }

    int Kp    = K >> 1;
    int PL    = (K >> 3) * N;
    int layer = local / PL;
    int r     = local - layer * PL;
    int kg    = r / N;
    int n     = r - kg * N;

    const float* s0 = src + (size_t)layer*K*N + (size_t)(kg*8)*N + n;
    float s[8];
#pragma unroll
    for (int t = 0; t < 8; t++) s[t] = s0[(size_t)t*N];
    uint32_t* d = dst + (size_t)layer*N*Kp + (size_t)n*Kp + kg*4;
    uint4 o;
    o.x = packh2(s[0], s[1]);
    o.y = packh2(s[2], s[3]);
    o.z = packh2(s[4], s[5]);
    o.w = packh2(s[6], s[7]);
    *(uint4*)d = o;
}

// ---------------------------------------------------------------------------
// Embedding (f32 residual stream)
// ---------------------------------------------------------------------------
__global__ void embed_kernel(const int* __restrict__ idx,
                             const float* __restrict__ tok,
                             const float* __restrict__ pos,
                             float* __restrict__ X)
{
    int i = blockIdx.x * blockDim.x + threadIdx.x;
    if (i >= MM * (CC/4)) return;
    int row = i / (CC/4);
    int c4  = i % (CC/4);
    int t   = idx[row];
    int p   = row & (TT-1);
    float4 a = *(const float4*)(tok + (size_t)t*CC + c4*4);
    float4 e = *(const float4*)(pos + (size_t)p*CC + c4*4);
    a.x += e.x; a.y += e.y; a.z += e.z; a.w += e.w;
    *(float4*)(X + (size_t)row*CC + c4*4) = a;
}

// ---------------------------------------------------------------------------
// LayerNorm: one warp per row; output fp16 packed.
// ---------------------------------------------------------------------------
__global__ void ln_kernel(const float* __restrict__ X,
                          const float* __restrict__ g,
                          const float* __restrict__ b,
                          uint32_t* __restrict__ Y)
{
    int row  = blockIdx.x * 8 + (threadIdx.x >> 5);
    int lane = threadIdx.x & 31;
    if (row >= MM) return;
    const float* x = X + (size_t)row*CC;
    float2 v[6];
    float s = 0.f, ss = 0.f;
#pragma unroll
    for (int j = 0; j < 6; j++) {
        int c = j*64 + 2*lane;
        v[j] = *(const float2*)(x + c);
        s  += v[j].x + v[j].y;
        ss += v[j].x*v[j].x + v[j].y*v[j].y;
    }
#pragma unroll
    for (int o = 16; o; o >>= 1) {
        s  += __shfl_xor_sync(0xFFFFFFFFu, s,  o);
        ss += __shfl_xor_sync(0xFFFFFFFFu, ss, o);
    }
    float mean = s  * (1.0f/CC);
    float var  = ss * (1.0f/CC) - mean*mean;
    float inv  = rsqrtf(var + 1e-5f);
    uint32_t* y = Y + (size_t)row*(CC/2);
#pragma unroll
    for (int j = 0; j < 6; j++) {
        int c = j*64 + 2*lane;
        float a0 = (v[j].x - mean)*inv*g[c    ] + b[c    ];
        float a1 = (v[j].y - mean)*inv*g[c + 1] + b[c + 1];
        y[j*32 + lane] = packh2(a0, a1);
    }
}

// ---------------------------------------------------------------------------
// Unified FP16 GEMM core: 64x128 CTA tile, BK=32 (16 kp), 128 threads,
// 4 warps of 32x64, 2-stage cp.async, 30 KB smem -> 4 CTAs/SM (16 warps/SM,
// DECOUPLED barriers across 4 CTAs). Proven best per-FLOP engine (tgemm64).
// OUTMODE: 0 = f32, 1 = tf32, 2 = fp16 packed.
// ---------------------------------------------------------------------------
struct GemmSmem64 {
    uint32_t As[2][64][20];    // 10240 B
    uint32_t Bs[2][128][20];   // 20480 B
};
#define SMEM_GEMM64 ((int)sizeof(GemmSmem64))   // 30720 bytes

template<bool RELU, bool RES, int OUTMODE>
__device__ __forceinline__
void gemm64_core(GemmSmem64* sm,
                 const uint32_t* __restrict__ A, const uint32_t* __restrict__ B,
                 const float* __restrict__ bias, const float* __restrict__ res,
                 void* __restrict__ Cv, int M, int N, int K, int bm, int bn)
{
    const int Kp   = K >> 1;
    const int tid  = threadIdx.x;
    const int lane = tid & 31;
    const int wid  = tid >> 5;
    const int wm = (wid & 1) * 32;
    const int wn = (wid >> 1) * 64;
    const int grp = lane >> 2;
    const int tg  = lane & 3;

    float acc[2][8][4];
#pragma unroll
    for (int mt = 0; mt < 2; mt++)
#pragma unroll
        for (int nt = 0; nt < 8; nt++)
#pragma unroll
            for (int e = 0; e < 4; e++) acc[mt][nt][e] = 0.f;

    auto issue = [&](int s, int k0p) {
#pragma unroll
        for (int p = 0; p < 2; p++) {          // A: 64 rows x 16 uints = 256 chunks
            int i  = tid + p*128;
            int r  = i >> 2;
            int c4 = (i & 3) * 4;
            cp_async16(&sm->As[s][r][c4], A + (size_t)(bm + r)*Kp + k0p + c4);
        }
#pragma unroll
        for (int p = 0; p < 4; p++) {          // B: 128 n x 16 uints = 512 chunks
            int i  = tid + p*128;
            int r  = i >> 2;
            int c4 = (i & 3) * 4;
            cp_async16(&sm->Bs[s][r][c4], B + (size_t)(bn + r)*Kp + k0p + c4);
        }
        CP_COMMIT();
    };

    const int nIter = K >> 5;
    issue(0, 0);

    for (int it = 0; it < nIter; it++) {
        const int cur = it & 1;
        CP_WAIT0();
        __syncthreads();
        if (it + 1 < nIter) issue(cur ^ 1, (it + 1) << 4);

#pragma unroll
        for (int kps = 0; kps < 16; kps += 8) {
            uint32_t af[2][4], bf[8][2];
#pragma unroll
            for (int mt = 0; mt < 2; mt++) {
                int r = wm + mt*16 + grp;
                af[mt][0] = sm->As[cur][r    ][kps + tg    ];
                af[mt][1] = sm->As[cur][r + 8][kps + tg    ];
                af[mt][2] = sm->As[cur][r    ][kps + tg + 4];
                af[mt][3] = sm->As[cur][r + 8][kps + tg + 4];
            }
#pragma unroll
            for (int nt = 0; nt < 8; nt++) {
                int c = wn + nt*8 + grp;
                bf[nt][0] = sm->Bs[cur][c][kps + tg    ];
                bf[nt][1] = sm->Bs[cur][c][kps + tg + 4];
            }
#pragma unroll
            for (int mt = 0; mt < 2; mt++)
#pragma unroll
                for (int nt = 0; nt < 8; nt++)
                    mma_f16(acc[mt][nt], af[mt], bf[nt]);
        }
    }

    // Epilogue
#pragma unroll
    for (int mt = 0; mt < 2; mt++) {
        int r0 = bm + wm + mt*16 + grp;
        int r1 = r0 + 8;
#pragma unroll
        for (int nt = 0; nt < 8; nt++) {
            int c = bn + wn + nt*8 + tg*2;
            float o0x = acc[mt][nt][0], o0y = acc[mt][nt][1];
            float o1x = acc[mt][nt][2], o1y = acc[mt][nt][3];
            if (bias) {
                float bv0 = bias[c], bv1 = bias[c+1];
                o0x += bv0; o0y += bv1; o1x += bv0; o1y += bv1;
            }
            if (RES) {
                float2 ra = *(const float2*)(res + (size_t)r0*N + c);
                float2 rb = *(const float2*)(res + (size_t)r1*N + c);
                o0x += ra.x; o0y += ra.y; o1x += rb.x; o1y += rb.y;
            }
            if (RELU) {
                o0x = fmaxf(o0x, 0.f); o0y = fmaxf(o0y, 0.f);
                o1x = fmaxf(o1x, 0.f); o1y = fmaxf(o1y, 0.f);
            }
            if (OUTMODE == 0) {
                float* C = (float*)Cv;
                float2 w0 = {o0x, o0y};
                float2 w1 = {o1x, o1y};
                *(float2*)(C + (size_t)r0*N + c) = w0;
                *(float2*)(C + (size_t)r1*N + c) = w1;
            } else if (OUTMODE == 1) {
                uint32_t* C = (uint32_t*)Cv;
                uint2 w0 = {f2tf(o0x), f2tf(o0y)};
                uint2 w1 = {f2tf(o1x), f2tf(o1y)};
                *(uint2*)(C + (size_t)r0*N + c) = w0;
                *(uint2*)(C + (size_t)r1*N + c) = w1;
            } else {
                uint32_t* C = (uint32_t*)Cv;
                C[(size_t)r0*(N>>1) + (c>>1)] = packh2(o0x, o0y);
                C[(size_t)r1*(N>>1) + (c>>1)] = packh2(o1x, o1y);
            }
        }
    }
}

template<bool RELU, bool RES, int OUTMODE>
__global__ __launch_bounds__(128, 4)
void tgemm64k(const uint32_t* __restrict__ A, const uint32_t* __restrict__ B,
              const float* __restrict__ bias, const float* __restrict__ res,
              void* __restrict__ C, int M, int N, int K)
{
    extern __shared__ GemmSmem64 sm64[];
    gemm64_core<RELU, RES, OUTMODE>(sm64, A, B, bias, res, C, M, N, K,
                                    blockIdx.y * 64, blockIdx.x * 128);
}

// Fused QKV: grid.x = 9 (3 matrices x 3 col-tiles of 128), grid.y = 128. tf32 out.
__global__ __launch_bounds__(128, 4)
void qkv_gemm(const uint32_t* __restrict__ A,
              const uint32_t* __restrict__ Wq, const uint32_t* __restrict__ Wk,
              const uint32_t* __restrict__ Wv,
              uint32_t* __restrict__ Q, uint32_t* __restrict__ Ko, uint32_t* __restrict__ V)
{
    extern __shared__ GemmSmem64 sm64[];
    int sel = blockIdx.x / 3;
    int bn  = (blockIdx.x % 3) * 128;
    const uint32_t* B = (sel == 0) ? Wq : (sel == 1) ? Wk : Wv;
    uint32_t*       C = (sel == 0) ? Q  : (sel == 1) ? Ko : V;
    gemm64_core<false, false, 1>(sm64, A, B, nullptr, nullptr, C,
                                 MM, CC, CC, blockIdx.y * 64, bn);
}

// ---------------------------------------------------------------------------
// Tensor-core flash attention; q/k/v tf32, att output fp16. (unchanged)
// ---------------------------------------------------------------------------
#define AKS 68
#define AVS 72
#define APS 36
#define ATT_SMEM ((TT*AKS + TT*AVS + 8*32*APS) * (int)sizeof(uint32_t))

__global__ __launch_bounds__(256, 1)
void attn_mma(const uint32_t* __restrict__ Q, const uint32_t* __restrict__ K,
              const uint32_t* __restrict__ V, uint32_t* __restrict__ O)
{
    extern __shared__ uint32_t sm[];
    uint32_t* Ks = sm;
    uint32_t* Vs = sm + TT*AKS;
    uint32_t* Pb = sm + TT*AKS + TT*AVS;

    const int bh = blockIdx.x;
    const int b  = bh / NH;
    const int h  = bh % NH;
    const float scale = 0.05103103630798288f;  // 1/sqrt(384)

    const int tid = threadIdx.x;
    const uint32_t* kbase = K + (size_t)b*TT*CC + h*HD;
    const uint32_t* vbase = V + (size_t)b*TT*CC + h*HD;

    for (int i = tid; i < TT*16; i += 256) {
        int t  = i >> 4;
        int d4 = (i & 15) * 4;
        *(uint4*)&Ks[t*AKS + d4] = *(const uint4*)(kbase + (size_t)t*CC + d4);
        *(uint4*)&Vs[t*AVS + d4] = *(const uint4*)(vbase + (size_t)t*CC + d4);
    }
    __syncthreads();

    const int lane = tid & 31;
    const int w    = tid >> 5;
    const int grp  = lane >> 2;
    const int tg   = lane & 3;
    const int q0   = w * 32;

    const uint32_t* qbase = Q + (size_t)b*TT*CC + h*HD;
    uint32_t qa[2][8][4];
#pragma unroll
    for (int mt = 0; mt < 2; mt++) {
        int ra = q0 + mt*16 + grp;
        int rb = ra + 8;
#pragma unroll
        for (int ks = 0; ks < 8; ks++) {
            int d = ks*8 + tg;
            qa[mt][ks][0] = qbase[(size_t)ra*CC + d    ];
            qa[mt][ks][1] = qbase[(size_t)rb*CC + d    ];
            qa[mt][ks][2] = qbase[(size_t)ra*CC + d + 4];
            qa[mt][ks][3] = qbase[(size_t)rb*CC + d + 4];
        }
    }

    float o[2][8][4];
#pragma unroll
    for (int mt = 0; mt < 2; mt++)
#pragma unroll
        for (int nt = 0; nt < 8; nt++)
#pragma unroll
            for (int e = 0; e < 4; e++) o[mt][nt][e] = 0.f;

    float mrow[2][2] = {{-1e30f,-1e30f},{-1e30f,-1e30f}};
    float lrow[2][2] = {{0.f,0.f},{0.f,0.f}};

    uint32_t* myP = Pb + w * 32 * APS;

    for (int j = 0; j <= w; j++) {
        const int kbeg = j * 32;
        float s[2][4][4];
#pragma unroll
        for (int mt = 0; mt < 2; mt++)
#pragma unroll
            for (int nt = 0; nt < 4; nt++)
#pragma unroll
                for (int e = 0; e < 4; e++) s[mt][nt][e] = 0.f;

#pragma unroll
        for (int ks = 0; ks < 8; ks++) {
            uint32_t bf[4][2];
#pragma unroll
            for (int nt = 0; nt < 4; nt++) {
                int key = kbeg + nt*8 + grp;
                int d   = ks*8 + tg;
                bf[nt][0] = Ks[key*AKS + d    ];
                bf[nt][1] = Ks[key*AKS + d + 4];
            }
#pragma unroll
            for (int mt = 0; mt < 2; mt++)
#pragma unroll
                for (int nt = 0; nt < 4; nt++)
                    mma_tf32(s[mt][nt], qa[mt][ks], bf[nt]);
        }

#pragma unroll
        for (int mt = 0; mt < 2; mt++) {
            int ra = q0 + mt*16 + grp;
            int rb = ra + 8;
            float rmax0 = -1e30f, rmax1 = -1e30f;
#pragma unroll
            for (int nt = 0; nt < 4; nt++) {
                int c0 = kbeg + nt*8 + 2*tg;
#pragma unroll
                for (int e = 0; e < 4; e++) {
                    float vv = s[mt][nt][e] * scale;
                    int col = c0 + (e & 1);
                    int row = (e < 2) ? ra : rb;
                    if (j == w && col > row) vv = -1e30f;
                    s[mt][nt][e] = vv;
                }
                rmax0 = fmaxf(rmax0, fmaxf(s[mt][nt][0], s[mt][nt][1]));
                rmax1 = fmaxf(rmax1, fmaxf(s[mt][nt][2], s[mt][nt][3]));
            }
            rmax0 = fmaxf(rmax0, __shfl_xor_sync(0xFFFFFFFFu, rmax0, 1));
            rmax0 = fmaxf(rmax0, __shfl_xor_sync(0xFFFFFFFFu, rmax0, 2));
            rmax1 = fmaxf(rmax1, __shfl_xor_sync(0xFFFFFFFFu, rmax1, 1));
            rmax1 = fmaxf(rmax1, __shfl_xor_sync(0xFFFFFFFFu, rmax1, 2));

            float mn0 = fmaxf(mrow[mt][0], rmax0);
            float mn1 = fmaxf(mrow[mt][1], rmax1);
            float cr0 = __expf(mrow[mt][0] - mn0);
            float cr1 = __expf(mrow[mt][1] - mn1);
            mrow[mt][0] = mn0; mrow[mt][1] = mn1;

            float rs0 = 0.f, rs1 = 0.f;
#pragma unroll
            for (int nt = 0; nt < 4; nt++) {
                float p0 = __expf(s[mt][nt][0] - mn0);
                float p1 = __expf(s[mt][nt][1] - mn0);
                float p2 = __expf(s[mt][nt][2] - mn1);
                float p3 = __expf(s[mt][nt][3] - mn1);
                rs0 += p0 + p1; rs1 += p2 + p3;
                int cb = nt*8 + 2*tg;
                myP[(mt*16 + grp    )*APS + cb    ] = f2tf(p0);
                myP[(mt*16 + grp    )*APS + cb + 1] = f2tf(p1);
                myP[(mt*16 + grp + 8)*APS + cb    ] = f2tf(p2);
                myP[(mt*16 + grp + 8)*APS + cb + 1] = f2tf(p3);
            }
            rs0 += __shfl_xor_sync(0xFFFFFFFFu, rs0, 1);
            rs0 += __shfl_xor_sync(0xFFFFFFFFu, rs0, 2);
            rs1 += __shfl_xor_sync(0xFFFFFFFFu, rs1, 1);
            rs1 += __shfl_xor_sync(0xFFFFFFFFu, rs1, 2);
            lrow[mt][0] = lrow[mt][0]*cr0 + rs0;
            lrow[mt][1] = lrow[mt][1]*cr1 + rs1;
#pragma unroll
            for (int nt = 0; nt < 8; nt++) {
                o[mt][nt][0] *= cr0; o[mt][nt][1] *= cr0;
                o[mt][nt][2] *= cr1; o[mt][nt][3] *= cr1;
            }
        }
        __syncwarp();

#pragma unroll
        for (int ks2 = 0; ks2 < 4; ks2++) {
            uint32_t vb[8][2];
#pragma unroll
            for (int nt = 0; nt < 8; nt++) {
                int key = kbeg + ks2*8 + tg;
                int d   = nt*8 + grp;
                vb[nt][0] = Vs[ key     *AVS + d];
                vb[nt][1] = Vs[(key + 4)*AVS + d];
            }
#pragma unroll
            for (int mt = 0; mt < 2; mt++) {
                uint32_t pa[4];
                pa[0] = myP[(mt*16 + grp    )*APS + ks2*8 + tg    ];
                pa[1] = myP[(mt*16 + grp + 8)*APS + ks2*8 + tg    ];
                pa[2] = myP[(mt*16 + grp    )*APS + ks2*8 + tg + 4];
                pa[3] = myP[(mt*16 + grp + 8)*APS + ks2*8 + tg + 4];
#pragma unroll
                for (int nt = 0; nt < 8; nt++)
                    mma_tf32(o[mt][nt], pa, vb[nt]);
            }
        }
        __syncwarp();
    }

    // Epilogue: att output fp16 packed [row][kp], Kp = CC/2 = 192.
    uint32_t* obase = O + (size_t)b*TT*(CC/2) + h*(HD/2);
#pragma unroll
    for (int mt = 0; mt < 2; mt++) {
        int ra = q0 + mt*16 + grp;
        int rb = ra + 8;
        float inv0 = 1.f / lrow[mt][0];
        float inv1 = 1.f / lrow[mt][1];
#pragma unroll
        for (int nt = 0; nt < 8; nt++) {
            int dp = nt*4 + tg;
            obase[(size_t)ra*(CC/2) + dp] = packh2(o[mt][nt][0]*inv0, o[mt][nt][1]*inv0);
            obase[(size_t)rb*(CC/2) + dp] = packh2(o[mt][nt][2]*inv1, o[mt][nt][3]*inv1);
        }
    }
}

// ---------------------------------------------------------------------------
// Host
// ---------------------------------------------------------------------------
extern "C" void kernel_launch(void* const* d_in, const int* in_sizes, int n_in,
                              void* d_out, int out_size)
{
    (void)in_sizes; (void)n_in; (void)out_size;

    const int*   idx     = (const int*)  d_in[0];
    const float* tok_emb = (const float*)d_in[1];
    const float* pos_emb = (const float*)d_in[2];
    const float* ln1_g   = (const float*)d_in[3];
    const float* ln1_b   = (const float*)d_in[4];
    const float* wq      = (const float*)d_in[5];
    const float* wk      = (const float*)d_in[6];
    const float* wv      = (const float*)d_in[7];
    const float* wo      = (const float*)d_in[8];
    const float* wo_b    = (const float*)d_in[9];
    const float* ln2_g   = (const float*)d_in[10];
    const float* ln2_b   = (const float*)d_in[11];
    const float* w1      = (const float*)d_in[12];
    const float* b1      = (const float*)d_in[13];
    const float* w2      = (const float*)d_in[14];
    const float* b2      = (const float*)d_in[15];
    const float* lnf_g   = (const float*)d_in[16];
    const float* lnf_b   = (const float*)d_in[17];
    const float* lm_w    = (const float*)d_in[18];
    const float* lm_b    = (const float*)d_in[19];
    float* out = (float*)d_out;

    float *x;
    uint32_t *h, *q, *k, *v, *att, *u, *wt;
    cudaGetSymbolAddress((void**)&x,   g_x);
    cudaGetSymbolAddress((void**)&h,   g_h);
    cudaGetSymbolAddress((void**)&q,   g_q);
    cudaGetSymbolAddress((void**)&k,   g_k);
    cudaGetSymbolAddress((void**)&v,   g_v);
    cudaGetSymbolAddress((void**)&att, g_att);
    cudaGetSymbolAddress((void**)&u,   g_u);
    cudaGetSymbolAddress((void**)&wt,  g_wt);

    cudaFuncSetAttribute(attn_mma, cudaFuncAttributeMaxDynamicSharedMemorySize, ATT_SMEM);
    cudaFuncSetAttribute(tgemm64k<false,false,0>, cudaFuncAttributeMaxDynamicSharedMemorySize, SMEM_GEMM64);
    cudaFuncSetAttribute(tgemm64k<false,true ,0>, cudaFuncAttributeMaxDynamicSharedMemorySize, SMEM_GEMM64);
    cudaFuncSetAttribute(tgemm64k<true ,false,2>, cudaFuncAttributeMaxDynamicSharedMemorySize, SMEM_GEMM64);
    cudaFuncSetAttribute(qkv_gemm,                cudaFuncAttributeMaxDynamicSharedMemorySize, SMEM_GEMM64);

    // Pre-convert + transpose all weights to fp16 [N][Kp] (single launch)
    cvt_trans_kernel<<<(R6 + 255)/256, 256>>>(wq, wk, wv, wo, w1, w2, lm_w, wt);

    {
        int total = MM * (CC/4);
        embed_kernel<<<(total + 255)/256, 256>>>(idx, tok_emb, pos_emb, x);
    }

    for (int L = 0; L < LL; L++) {
        const float* g1  = ln1_g + (size_t)L*CC;
        const float* bg1 = ln1_b + (size_t)L*CC;
        const uint32_t* Wq = wt + OFF16_WQ + (size_t)L*(CC*CC/2);
        const uint32_t* Wk = wt + OFF16_WK + (size_t)L*(CC*CC/2);
        const uint32_t* Wv = wt + OFF16_WV + (size_t)L*(CC*CC/2);
        const uint32_t* Wo = wt + OFF16_WO + (size_t)L*(CC*CC/2);
        const float* Wob = wo_b + (size_t)L*CC;
        const float* g2  = ln2_g + (size_t)L*CC;
        const float* bg2 = ln2_b + (size_t)L*CC;
        const uint32_t* W1 = wt + OFF16_W1 + (size_t)L*(CC*FF/2);
        const float* B1  = b1 + (size_t)L*FF;
        const uint32_t* W2 = wt + OFF16_W2 + (size_t)L*(FF*CC/2);
        const float* B2  = b2 + (size_t)L*CC;

        ln_kernel<<<MM/8, 256>>>(x, g1, bg1, h);
        qkv_gemm<<<dim3(9, MM/64), 128, SMEM_GEMM64>>>(h, Wq, Wk, Wv, q, k, v);
        attn_mma<<<BB*NH, 256, ATT_SMEM>>>(q, k, v, att);
        // x += att @ Wo + wo_b
        tgemm64k<false,true,0><<<dim3(CC/128, MM/64), 128, SMEM_GEMM64>>>(
            att, Wo, Wob, x, x, MM, CC, CC);
        ln_kernel<<<MM/8, 256>>>(x, g2, bg2, h);
        // u = relu(h @ W1 + b1), fp16 out
        tgemm64k<true,false,2><<<dim3(FF/128, MM/64), 128, SMEM_GEMM64>>>(
            h, W1, B1, nullptr, u, MM, FF, CC);
        // x += u @ W2 + b2
        tgemm64k<false,true,0><<<dim3(CC/128, MM/64), 128, SMEM_GEMM64>>>(
            u, W2, B2, x, x, MM, CC, FF);
    }

    ln_kernel<<<MM/8, 256>>>(x, lnf_g, lnf_b, h);
    // logits = h @ lm_w + lm_b
    tgemm64k<false,false,0><<<dim3(VV/128, MM/64), 128, SMEM_GEMM64>>>(
        h, wt + OFF16_LM, lm_b, nullptr, out, MM, VV, CC);
}

// round 17
// speedup vs baseline: 1.1646x; 1.1434x over previous
#include <cuda_runtime.h>
#include <cuda_fp16.h>
#include <math.h>
#include <stdint.h>

// Problem dims
#define BB 32
#define TT 256
#define CC 384
#define LL 6
#define NH 6
#define HD 64
#define VV 32000
#define MM (BB*TT)      // 8192
#define FF (4*CC)       // 1536

// fp16 weight scratch layout (uint32 = half2 units), stored TRANSPOSED [N][Kp]
#define OFF16_WQ 0
#define OFF16_WK 442368
#define OFF16_WV 884736
#define OFF16_WO 1327104
#define OFF16_W1 1769472
#define OFF16_W2 3538944
#define OFF16_LM 5308416
#define WT16_TOTAL 11452416

// Scratch (device globals; no allocations allowed)
__device__ float    g_x[MM*CC];          // residual stream (f32)
__device__ uint32_t g_h[MM*CC/2];        // LN output (fp16 packed, Kp=192)
__device__ uint32_t g_q[MM*CC];          // tf32 (attention input)
__device__ uint32_t g_k[MM*CC];
__device__ uint32_t g_v[MM*CC];
__device__ uint32_t g_att[MM*CC/2];      // fp16 packed
__device__ uint32_t g_u[MM*FF/2];        // fp16 packed
__device__ uint32_t g_wt[WT16_TOTAL];    // fp16 transposed weights

// ---------------------------------------------------------------------------
// Helpers
// ---------------------------------------------------------------------------
__device__ __forceinline__ uint32_t f2tf(float f) {
    uint32_t u;
    asm("cvt.rna.tf32.f32 %0, %1;" : "=r"(u) : "f"(f));
    return u;
}

__device__ __forceinline__ uint32_t packh2(float lo, float hi) {
    __half2 h = __floats2half2_rn(lo, hi);
    return *(uint32_t*)&h;
}

__device__ __forceinline__ void mma_tf32(float* c, const uint32_t* a, const uint32_t* b) {
    asm volatile(
        "mma.sync.aligned.m16n8k8.row.col.f32.tf32.tf32.f32 "
        "{%0,%1,%2,%3}, {%4,%5,%6,%7}, {%8,%9}, {%0,%1,%2,%3};"
        : "+f"(c[0]), "+f"(c[1]), "+f"(c[2]), "+f"(c[3])
        : "r"(a[0]), "r"(a[1]), "r"(a[2]), "r"(a[3]),
          "r"(b[0]), "r"(b[1]));
}

__device__ __forceinline__ void mma_f16(float* c, const uint32_t* a, const uint32_t* b) {
    asm volatile(
        "mma.sync.aligned.m16n8k16.row.col.f32.f16.f16.f32 "
        "{%0,%1,%2,%3}, {%4,%5,%6,%7}, {%8,%9}, {%0,%1,%2,%3};"
        : "+f"(c[0]), "+f"(c[1]), "+f"(c[2]), "+f"(c[3])
        : "r"(a[0]), "r"(a[1]), "r"(a[2]), "r"(a[3]),
          "r"(b[0]), "r"(b[1]));
}

__device__ __forceinline__ void cp_async16(void* sptr, const void* gptr) {
    uint32_t sa = (uint32_t)__cvta_generic_to_shared(sptr);
    asm volatile("cp.async.cg.shared.global [%0], [%1], 16;\n" :: "r"(sa), "l"(gptr));
}
#define CP_COMMIT() asm volatile("cp.async.commit_group;\n" ::: "memory")
#define CP_WAIT0()  asm volatile("cp.async.wait_group 0;\n" ::: "memory")

// ---------------------------------------------------------------------------
// Fused transpose + fp16 convert of ALL weights, one launch.
// ---------------------------------------------------------------------------
#define R0 110592
#define R1 221184
#define R2 331776
#define R3 442368
#define R4 884736
#define R5 1327104
#define R6 2863104

__global__ void cvt_trans_kernel(const float* __restrict__ wq, const float* __restrict__ wk,
                                 const float* __restrict__ wv, const float* __restrict__ wo,
                                 const float* __restrict__ w1, const float* __restrict__ w2,
                                 const float* __restrict__ lm, uint32_t* __restrict__ wt)
{
    int f = blockIdx.x * blockDim.x + threadIdx.x;
    if (f >= R6) return;
    const float* src; uint32_t* dst; int K, N, local;
    if (f < R0)      { src = wq; dst = wt + OFF16_WQ; K = CC; N = CC; local = f; }
    else if (f < R1) { src = wk; dst = wt + OFF16_WK; K = CC; N = CC; local = f - R0; }
    else if (f < R2) { src = wv; dst = wt + OFF16_WV; K = CC; N = CC; local = f - R1; }
    else if (f < R3) { src = wo; dst = wt + OFF16_WO; K = CC; N = CC; local = f - R2; }
    else if (f < R4) { src = w1; dst = wt + OFF16_W1; K = CC; N = FF; local = f - R3; }
    else if (f < R5) { src = w2; dst = wt + OFF16_W2; K = FF; N = CC; local = f - R4; }
    else             { src = lm; dst = wt + OFF16_LM; K = CC; N = VV; local = f - R5; }

    int Kp    = K >> 1;
    int PL    = (K >> 3) * N;
    int layer = local / PL;
    int r     = local - layer * PL;
    int kg    = r / N;
    int n     = r - kg * N;

    const float* s0 = src + (size_t)layer*K*N + (size_t)(kg*8)*N + n;
    float s[8];
#pragma unroll
    for (int t = 0; t < 8; t++) s[t] = s0[(size_t)t*N];
    uint32_t* d = dst + (size_t)layer*N*Kp + (size_t)n*Kp + kg*4;
    uint4 o;
    o.x = packh2(s[0], s[1]);
    o.y = packh2(s[2], s[3]);
    o.z = packh2(s[4], s[5]);
    o.w = packh2(s[6], s[7]);
    *(uint4*)d = o;
}

// ---------------------------------------------------------------------------
// Embedding (f32 residual stream)
// ---------------------------------------------------------------------------
__global__ void embed_kernel(const int* __restrict__ idx,
                             const float* __restrict__ tok,
                             const float* __restrict__ pos,
                             float* __restrict__ X)
{
    int i = blockIdx.x * blockDim.x + threadIdx.x;
    if (i >= MM * (CC/4)) return;
    int row = i / (CC/4);
    int c4  = i % (CC/4);
    int t   = idx[row];
    int p   = row & (TT-1);
    float4 a = *(const float4*)(tok + (size_t)t*CC + c4*4);
    float4 e = *(const float4*)(pos + (size_t)p*CC + c4*4);
    a.x += e.x; a.y += e.y; a.z += e.z; a.w += e.w;
    *(float4*)(X + (size_t)row*CC + c4*4) = a;
}

// ---------------------------------------------------------------------------
// LayerNorm: one warp per row; output fp16 packed.
// ---------------------------------------------------------------------------
__global__ void ln_kernel(const float* __restrict__ X,
                          const float* __restrict__ g,
                          const float* __restrict__ b,
                          uint32_t* __restrict__ Y)
{
    int row  = blockIdx.x * 8 + (threadIdx.x >> 5);
    int lane = threadIdx.x & 31;
    if (row >= MM) return;
    const float* x = X + (size_t)row*CC;
    float2 v[6];
    float s = 0.f, ss = 0.f;
#pragma unroll
    for (int j = 0; j < 6; j++) {
        int c = j*64 + 2*lane;
        v[j] = *(const float2*)(x + c);
        s  += v[j].x + v[j].y;
        ss += v[j].x*v[j].x + v[j].y*v[j].y;
    }
#pragma unroll
    for (int o = 16; o; o >>= 1) {
        s  += __shfl_xor_sync(0xFFFFFFFFu, s,  o);
        ss += __shfl_xor_sync(0xFFFFFFFFu, ss, o);
    }
    float mean = s  * (1.0f/CC);
    float var  = ss * (1.0f/CC) - mean*mean;
    float inv  = rsqrtf(var + 1e-5f);
    uint32_t* y = Y + (size_t)row*(CC/2);
#pragma unroll
    for (int j = 0; j < 6; j++) {
        int c = j*64 + 2*lane;
        float a0 = (v[j].x - mean)*inv*g[c    ] + b[c    ];
        float a1 = (v[j].y - mean)*inv*g[c + 1] + b[c + 1];
        y[j*32 + lane] = packh2(a0, a1);
    }
}

// ---------------------------------------------------------------------------
// FP16 GEMM (round-12 config, BK 32 -> 64): 128x128 tile, BK=64 (32 kp),
// 128 threads, 4 warps of 64x64, 2-stage cp.async. Halves the number of
// barrier/wait boundaries per K and doubles latency cover per stage.
// OUTMODE: 0 = f32, 1 = tf32, 2 = fp16 packed.
// ---------------------------------------------------------------------------
struct GemmSmemH {
    uint32_t As[2][128][36];   // 36864 B  (32 kp + pad4; 144B rows, 16B-aligned)
    uint32_t Bs[2][128][36];   // 36864 B
};
#define SMEM_GEMMH ((int)sizeof(GemmSmemH))   // 73728 bytes -> 2 CTAs/SM

template<bool RELU, bool RES, int OUTMODE>
__device__ __forceinline__
void gemm_core(GemmSmemH* sm,
               const uint32_t* __restrict__ A, const uint32_t* __restrict__ B,
               const float* __restrict__ bias, const float* __restrict__ res,
               void* __restrict__ Cv, int M, int N, int K, int bm, int bn)
{
    const int Kp   = K >> 1;
    const int tid  = threadIdx.x;
    const int lane = tid & 31;
    const int wid  = tid >> 5;
    const int wm = (wid & 1) * 64;
    const int wn = (wid >> 1) * 64;
    const int grp = lane >> 2;
    const int tg  = lane & 3;

    float acc[4][8][4];
#pragma unroll
    for (int mt = 0; mt < 4; mt++)
#pragma unroll
        for (int nt = 0; nt < 8; nt++)
#pragma unroll
            for (int e = 0; e < 4; e++) acc[mt][nt][e] = 0.f;

    auto issue = [&](int s, int k0p) {
#pragma unroll
        for (int p = 0; p < 8; p++) {          // A: 128 rows x 32 uints = 1024 chunks
            int i  = tid + p*128;
            int r  = i >> 3;
            int c4 = (i & 7) * 4;
            cp_async16(&sm->As[s][r][c4], A + (size_t)(bm + r)*Kp + k0p + c4);
        }
#pragma unroll
        for (int p = 0; p < 8; p++) {          // B: 128 n x 32 uints
            int i  = tid + p*128;
            int r  = i >> 3;
            int c4 = (i & 7) * 4;
            cp_async16(&sm->Bs[s][r][c4], B + (size_t)(bn + r)*Kp + k0p + c4);
        }
        CP_COMMIT();
    };

    const int nIter = K >> 6;     // BK=64
    issue(0, 0);

    for (int it = 0; it < nIter; it++) {
        const int cur = it & 1;
        CP_WAIT0();
        __syncthreads();
        if (it + 1 < nIter) issue(cur ^ 1, (it + 1) << 5);

#pragma unroll
        for (int kps = 0; kps < 32; kps += 8) {
            uint32_t af[4][4], bf[8][2];
#pragma unroll
            for (int mt = 0; mt < 4; mt++) {
                int r = wm + mt*16 + grp;
                af[mt][0] = sm->As[cur][r    ][kps + tg    ];
                af[mt][1] = sm->As[cur][r + 8][kps + tg    ];
                af[mt][2] = sm->As[cur][r    ][kps + tg + 4];
                af[mt][3] = sm->As[cur][r + 8][kps + tg + 4];
            }
#pragma unroll
            for (int nt = 0; nt < 8; nt++) {
                int c = wn + nt*8 + grp;
                bf[nt][0] = sm->Bs[cur][c][kps + tg    ];
                bf[nt][1] = sm->Bs[cur][c][kps + tg + 4];
            }
#pragma unroll
            for (int mt = 0; mt < 4; mt++)
#pragma unroll
                for (int nt = 0; nt < 8; nt++)
                    mma_f16(acc[mt][nt], af[mt], bf[nt]);
        }
    }

    // Epilogue
#pragma unroll
    for (int mt = 0; mt < 4; mt++) {
        int r0 = bm + wm + mt*16 + grp;
        int r1 = r0 + 8;
#pragma unroll
        for (int nt = 0; nt < 8; nt++) {
            int c = bn + wn + nt*8 + tg*2;
            float o0x = acc[mt][nt][0], o0y = acc[mt][nt][1];
            float o1x = acc[mt][nt][2], o1y = acc[mt][nt][3];
            if (bias) {
                float bv0 = bias[c], bv1 = bias[c+1];
                o0x += bv0; o0y += bv1; o1x += bv0; o1y += bv1;
            }
            if (RES) {
                float2 ra = *(const float2*)(res + (size_t)r0*N + c);
                float2 rb = *(const float2*)(res + (size_t)r1*N + c);
                o0x += ra.x; o0y += ra.y; o1x += rb.x; o1y += rb.y;
            }
            if (RELU) {
                o0x = fmaxf(o0x, 0.f); o0y = fmaxf(o0y, 0.f);
                o1x = fmaxf(o1x, 0.f); o1y = fmaxf(o1y, 0.f);
            }
            if (OUTMODE == 0) {
                float* C = (float*)Cv;
                float2 w0 = {o0x, o0y};
                float2 w1 = {o1x, o1y};
                *(float2*)(C + (size_t)r0*N + c) = w0;
                *(float2*)(C + (size_t)r1*N + c) = w1;
            } else if (OUTMODE == 1) {
                uint32_t* C = (uint32_t*)Cv;
                uint2 w0 = {f2tf(o0x), f2tf(o0y)};
                uint2 w1 = {f2tf(o1x), f2tf(o1y)};
                *(uint2*)(C + (size_t)r0*N + c) = w0;
                *(uint2*)(C + (size_t)r1*N + c) = w1;
            } else {
                uint32_t* C = (uint32_t*)Cv;
                C[(size_t)r0*(N>>1) + (c>>1)] = packh2(o0x, o0y);
                C[(size_t)r1*(N>>1) + (c>>1)] = packh2(o1x, o1y);
            }
        }
    }
}

template<bool RELU, bool RES, int OUTMODE>
__global__ __launch_bounds__(128)
void tgemm(const uint32_t* __restrict__ A, const uint32_t* __restrict__ B,
           const float* __restrict__ bias, const float* __restrict__ res,
           void* __restrict__ C, int M, int N, int K)
{
    extern __shared__ GemmSmemH smg[];
    gemm_core<RELU, RES, OUTMODE>(smg, A, B, bias, res, C, M, N, K,
                                  blockIdx.y * 128, blockIdx.x * 128);
}

// Fused QKV: grid.x = 9 (3 matrices x 3 col-tiles), grid.y = 64. tf32 out.
__global__ __launch_bounds__(128)
void qkv_gemm(const uint32_t* __restrict__ A,
              const uint32_t* __restrict__ Wq, const uint32_t* __restrict__ Wk,
              const uint32_t* __restrict__ Wv,
              uint32_t* __restrict__ Q, uint32_t* __restrict__ Ko, uint32_t* __restrict__ V)
{
    extern __shared__ GemmSmemH smg[];
    int sel = blockIdx.x / 3;
    int bn  = (blockIdx.x % 3) * 128;
    const uint32_t* B = (sel == 0) ? Wq : (sel == 1) ? Wk : Wv;
    uint32_t*       C = (sel == 0) ? Q  : (sel == 1) ? Ko : V;
    gemm_core<false, false, 1>(smg, A, B, nullptr, nullptr, C,
                               MM, CC, CC, blockIdx.y * 128, bn);
}

// ---------------------------------------------------------------------------
// Small-M-tile FP16 GEMM for N=384 projections (Wo, W2): 64x128 tile, BK=64,
// 4 warps of 32x64, 2-stage cp.async, 4 CTAs/SM (221 KB total smem).
// bias+residual, f32 out.
// ---------------------------------------------------------------------------
struct GemmSmemH64 {
    uint32_t As[2][64][36];    // 18432 B
    uint32_t Bs[2][128][36];   // 36864 B
};
#define SMEM_GEMMH64 ((int)sizeof(GemmSmemH64))   // 55296 bytes

__global__ __launch_bounds__(128, 4)
void tgemm64(const uint32_t* __restrict__ A, const uint32_t* __restrict__ B,
             const float* __restrict__ bias, const float* __restrict__ res,
             float* __restrict__ C, int M, int N, int K)
{
    extern __shared__ GemmSmemH64 sm64[];
    GemmSmemH64* sm = sm64;

    const int Kp   = K >> 1;
    const int bm = blockIdx.y * 64;
    const int bn = blockIdx.x * 128;
    const int tid  = threadIdx.x;
    const int lane = tid & 31;
    const int wid  = tid >> 5;
    const int wm = (wid & 1) * 32;
    const int wn = (wid >> 1) * 64;
    const int grp = lane >> 2;
    const int tg  = lane & 3;

    float acc[2][8][4];
#pragma unroll
    for (int mt = 0; mt < 2; mt++)
#pragma unroll
        for (int nt = 0; nt < 8; nt++)
#pragma unroll
            for (int e = 0; e < 4; e++) acc[mt][nt][e] = 0.f;

    auto issue = [&](int s, int k0p) {
#pragma unroll
        for (int p = 0; p < 4; p++) {          // A: 64 rows x 32 uints = 512 chunks
            int i  = tid + p*128;
            int r  = i >> 3;
            int c4 = (i & 7) * 4;
            cp_async16(&sm->As[s][r][c4], A + (size_t)(bm + r)*Kp + k0p + c4);
        }
#pragma unroll
        for (int p = 0; p < 8; p++) {          // B: 128 n x 32 uints = 1024 chunks
            int i  = tid + p*128;
            int r  = i >> 3;
            int c4 = (i & 7) * 4;
            cp_async16(&sm->Bs[s][r][c4], B + (size_t)(bn + r)*Kp + k0p + c4);
        }
        CP_COMMIT();
    };

    const int nIter = K >> 6;
    issue(0, 0);

    for (int it = 0; it < nIter; it++) {
        const int cur = it & 1;
        CP_WAIT0();
        __syncthreads();
        if (it + 1 < nIter) issue(cur ^ 1, (it + 1) << 5);

#pragma unroll
        for (int kps = 0; kps < 32; kps += 8) {
            uint32_t af[2][4], bf[8][2];
#pragma unroll
            for (int mt = 0; mt < 2; mt++) {
                int r = wm + mt*16 + grp;
                af[mt][0] = sm->As[cur][r    ][kps + tg    ];
                af[mt][1] = sm->As[cur][r + 8][kps + tg    ];
                af[mt][2] = sm->As[cur][r    ][kps + tg + 4];
                af[mt][3] = sm->As[cur][r + 8][kps + tg + 4];
            }
#pragma unroll
            for (int nt = 0; nt < 8; nt++) {
                int c = wn + nt*8 + grp;
                bf[nt][0] = sm->Bs[cur][c][kps + tg    ];
                bf[nt][1] = sm->Bs[cur][c][kps + tg + 4];
            }
#pragma unroll
            for (int mt = 0; mt < 2; mt++)
#pragma unroll
                for (int nt = 0; nt < 8; nt++)
                    mma_f16(acc[mt][nt], af[mt], bf[nt]);
        }
    }

#pragma unroll
    for (int mt = 0; mt < 2; mt++) {
        int r0 = bm + wm + mt*16 + grp;
        int r1 = r0 + 8;
#pragma unroll
        for (int nt = 0; nt < 8; nt++) {
            int c = bn + wn + nt*8 + tg*2;
            float bv0 = bias[c], bv1 = bias[c+1];
            float2 ra = *(const float2*)(res + (size_t)r0*N + c);
            float2 rb = *(const float2*)(res + (size_t)r1*N + c);
            float2 w0 = {acc[mt][nt][0] + bv0 + ra.x, acc[mt][nt][1] + bv1 + ra.y};
            float2 w1 = {acc[mt][nt][2] + bv0 + rb.x, acc[mt][nt][3] + bv1 + rb.y};
            *(float2*)(C + (size_t)r0*N + c) = w0;
            *(float2*)(C + (size_t)r1*N + c) = w1;
        }
    }
}

// ---------------------------------------------------------------------------
// Tensor-core flash attention; q/k/v tf32, att output fp16. (unchanged)
// ---------------------------------------------------------------------------
#define AKS 68
#define AVS 72
#define APS 36
#define ATT_SMEM ((TT*AKS + TT*AVS + 8*32*APS) * (int)sizeof(uint32_t))

__global__ __launch_bounds__(256, 1)
void attn_mma(const uint32_t* __restrict__ Q, const uint32_t* __restrict__ K,
              const uint32_t* __restrict__ V, uint32_t* __restrict__ O)
{
    extern __shared__ uint32_t sm[];
    uint32_t* Ks = sm;
    uint32_t* Vs = sm + TT*AKS;
    uint32_t* Pb = sm + TT*AKS + TT*AVS;

    const int bh = blockIdx.x;
    const int b  = bh / NH;
    const int h  = bh % NH;
    const float scale = 0.05103103630798288f;  // 1/sqrt(384)

    const int tid = threadIdx.x;
    const uint32_t* kbase = K + (size_t)b*TT*CC + h*HD;
    const uint32_t* vbase = V + (size_t)b*TT*CC + h*HD;

    for (int i = tid; i < TT*16; i += 256) {
        int t  = i >> 4;
        int d4 = (i & 15) * 4;
        *(uint4*)&Ks[t*AKS + d4] = *(const uint4*)(kbase + (size_t)t*CC + d4);
        *(uint4*)&Vs[t*AVS + d4] = *(const uint4*)(vbase + (size_t)t*CC + d4);
    }
    __syncthreads();

    const int lane = tid & 31;
    const int w    = tid >> 5;
    const int grp  = lane >> 2;
    const int tg   = lane & 3;
    const int q0   = w * 32;

    const uint32_t* qbase = Q + (size_t)b*TT*CC + h*HD;
    uint32_t qa[2][8][4];
#pragma unroll
    for (int mt = 0; mt < 2; mt++) {
        int ra = q0 + mt*16 + grp;
        int rb = ra + 8;
#pragma unroll
        for (int ks = 0; ks < 8; ks++) {
            int d = ks*8 + tg;
            qa[mt][ks][0] = qbase[(size_t)ra*CC + d    ];
            qa[mt][ks][1] = qbase[(size_t)rb*CC + d    ];
            qa[mt][ks][2] = qbase[(size_t)ra*CC + d + 4];
            qa[mt][ks][3] = qbase[(size_t)rb*CC + d + 4];
        }
    }

    float o[2][8][4];
#pragma unroll
    for (int mt = 0; mt < 2; mt++)
#pragma unroll
        for (int nt = 0; nt < 8; nt++)
#pragma unroll
            for (int e = 0; e < 4; e++) o[mt][nt][e] = 0.f;

    float mrow[2][2] = {{-1e30f,-1e30f},{-1e30f,-1e30f}};
    float lrow[2][2] = {{0.f,0.f},{0.f,0.f}};

    uint32_t* myP = Pb + w * 32 * APS;

    for (int j = 0; j <= w; j++) {
        const int kbeg = j * 32;
        float s[2][4][4];
#pragma unroll
        for (int mt = 0; mt < 2; mt++)
#pragma unroll
            for (int nt = 0; nt < 4; nt++)
#pragma unroll
                for (int e = 0; e < 4; e++) s[mt][nt][e] = 0.f;

#pragma unroll
        for (int ks = 0; ks < 8; ks++) {
            uint32_t bf[4][2];
#pragma unroll
            for (int nt = 0; nt < 4; nt++) {
                int key = kbeg + nt*8 + grp;
                int d   = ks*8 + tg;
                bf[nt][0] = Ks[key*AKS + d    ];
                bf[nt][1] = Ks[key*AKS + d + 4];
            }
#pragma unroll
            for (int mt = 0; mt < 2; mt++)
#pragma unroll
                for (int nt = 0; nt < 4; nt++)
                    mma_tf32(s[mt][nt], qa[mt][ks], bf[nt]);
        }

#pragma unroll
        for (int mt = 0; mt < 2; mt++) {
            int ra = q0 + mt*16 + grp;
            int rb = ra + 8;
            float rmax0 = -1e30f, rmax1 = -1e30f;
#pragma unroll
            for (int nt = 0; nt < 4; nt++) {
                int c0 = kbeg + nt*8 + 2*tg;
#pragma unroll
                for (int e = 0; e < 4; e++) {
                    float vv = s[mt][nt][e] * scale;
                    int col = c0 + (e & 1);
                    int row = (e < 2) ? ra : rb;
                    if (j == w && col > row) vv = -1e30f;
                    s[mt][nt][e] = vv;
                }
                rmax0 = fmaxf(rmax0, fmaxf(s[mt][nt][0], s[mt][nt][1]));
                rmax1 = fmaxf(rmax1, fmaxf(s[mt][nt][2], s[mt][nt][3]));
            }
            rmax0 = fmaxf(rmax0, __shfl_xor_sync(0xFFFFFFFFu, rmax0, 1));
            rmax0 = fmaxf(rmax0, __shfl_xor_sync(0xFFFFFFFFu, rmax0, 2));
            rmax1 = fmaxf(rmax1, __shfl_xor_sync(0xFFFFFFFFu, rmax1, 1));
            rmax1 = fmaxf(rmax1, __shfl_xor_sync(0xFFFFFFFFu, rmax1, 2));

            float mn0 = fmaxf(mrow[mt][0], rmax0);
            float mn1 = fmaxf(mrow[mt][1], rmax1);
            float cr0 = __expf(mrow[mt][0] - mn0);
            float cr1 = __expf(mrow[mt][1] - mn1);
            mrow[mt][0] = mn0; mrow[mt][1] = mn1;

            float rs0 = 0.f, rs1 = 0.f;
#pragma unroll
            for (int nt = 0; nt < 4; nt++) {
                float p0 = __expf(s[mt][nt][0] - mn0);
                float p1 = __expf(s[mt][nt][1] - mn0);
                float p2 = __expf(s[mt][nt][2] - mn1);
                float p3 = __expf(s[mt][nt][3] - mn1);
                rs0 += p0 + p1; rs1 += p2 + p3;
                int cb = nt*8 + 2*tg;
                myP[(mt*16 + grp    )*APS + cb    ] = f2tf(p0);
                myP[(mt*16 + grp    )*APS + cb + 1] = f2tf(p1);
                myP[(mt*16 + grp + 8)*APS + cb    ] = f2tf(p2);
                myP[(mt*16 + grp + 8)*APS + cb + 1] = f2tf(p3);
            }
            rs0 += __shfl_xor_sync(0xFFFFFFFFu, rs0, 1);
            rs0 += __shfl_xor_sync(0xFFFFFFFFu, rs0, 2);
            rs1 += __shfl_xor_sync(0xFFFFFFFFu, rs1, 1);
            rs1 += __shfl_xor_sync(0xFFFFFFFFu, rs1, 2);
            lrow[mt][0] = lrow[mt][0]*cr0 + rs0;
            lrow[mt][1] = lrow[mt][1]*cr1 + rs1;
#pragma unroll
            for (int nt = 0; nt < 8; nt++) {
                o[mt][nt][0] *= cr0; o[mt][nt][1] *= cr0;
                o[mt][nt][2] *= cr1; o[mt][nt][3] *= cr1;
            }
        }
        __syncwarp();

#pragma unroll
        for (int ks2 = 0; ks2 < 4; ks2++) {
            uint32_t vb[8][2];
#pragma unroll
            for (int nt = 0; nt < 8; nt++) {
                int key = kbeg + ks2*8 + tg;
                int d   = nt*8 + grp;
                vb[nt][0] = Vs[ key     *AVS + d];
                vb[nt][1] = Vs[(key + 4)*AVS + d];
            }
#pragma unroll
            for (int mt = 0; mt < 2; mt++) {
                uint32_t pa[4];
                pa[0] = myP[(mt*16 + grp    )*APS + ks2*8 + tg    ];
                pa[1] = myP[(mt*16 + grp + 8)*APS + ks2*8 + tg    ];
                pa[2] = myP[(mt*16 + grp    )*APS + ks2*8 + tg + 4];
                pa[3] = myP[(mt*16 + grp + 8)*APS + ks2*8 + tg + 4];
#pragma unroll
                for (int nt = 0; nt < 8; nt++)
                    mma_tf32(o[mt][nt], pa, vb[nt]);
            }
        }
        __syncwarp();
    }

    // Epilogue: att output fp16 packed [row][kp], Kp = CC/2 = 192.
    uint32_t* obase = O + (size_t)b*TT*(CC/2) + h*(HD/2);
#pragma unroll
    for (int mt = 0; mt < 2; mt++) {
        int ra = q0 + mt*16 + grp;
        int rb = ra + 8;
        float inv0 = 1.f / lrow[mt][0];
        float inv1 = 1.f / lrow[mt][1];
#pragma unroll
        for (int nt = 0; nt < 8; nt++) {
            int dp = nt*4 + tg;
            obase[(size_t)ra*(CC/2) + dp] = packh2(o[mt][nt][0]*inv0, o[mt][nt][1]*inv0);
            obase[(size_t)rb*(CC/2) + dp] = packh2(o[mt][nt][2]*inv1, o[mt][nt][3]*inv1);
        }
    }
}

// ---------------------------------------------------------------------------
// Host
// ---------------------------------------------------------------------------
extern "C" void kernel_launch(void* const* d_in, const int* in_sizes, int n_in,
                              void* d_out, int out_size)
{
    (void)in_sizes; (void)n_in; (void)out_size;

    const int*   idx     = (const int*)  d_in[0];
    const float* tok_emb = (const float*)d_in[1];
    const float* pos_emb = (const float*)d_in[2];
    const float* ln1_g   = (const float*)d_in[3];
    const float* ln1_b   = (const float*)d_in[4];
    const float* wq      = (const float*)d_in[5];
    const float* wk      = (const float*)d_in[6];
    const float* wv      = (const float*)d_in[7];
    const float* wo      = (const float*)d_in[8];
    const float* wo_b    = (const float*)d_in[9];
    const float* ln2_g   = (const float*)d_in[10];
    const float* ln2_b   = (const float*)d_in[11];
    const float* w1      = (const float*)d_in[12];
    const float* b1      = (const float*)d_in[13];
    const float* w2      = (const float*)d_in[14];
    const float* b2      = (const float*)d_in[15];
    const float* lnf_g   = (const float*)d_in[16];
    const float* lnf_b   = (const float*)d_in[17];
    const float* lm_w    = (const float*)d_in[18];
    const float* lm_b    = (const float*)d_in[19];
    float* out = (float*)d_out;

    float *x;
    uint32_t *h, *q, *k, *v, *att, *u, *wt;
    cudaGetSymbolAddress((void**)&x,   g_x);
    cudaGetSymbolAddress((void**)&h,   g_h);
    cudaGetSymbolAddress((void**)&q,   g_q);
    cudaGetSymbolAddress((void**)&k,   g_k);
    cudaGetSymbolAddress((void**)&v,   g_v);
    cudaGetSymbolAddress((void**)&att, g_att);
    cudaGetSymbolAddress((void**)&u,   g_u);
    cudaGetSymbolAddress((void**)&wt,  g_wt);

    cudaFuncSetAttribute(attn_mma, cudaFuncAttributeMaxDynamicSharedMemorySize, ATT_SMEM);
    cudaFuncSetAttribute(tgemm<false,false,0>, cudaFuncAttributeMaxDynamicSharedMemorySize, SMEM_GEMMH);
    cudaFuncSetAttribute(tgemm<true ,false,2>, cudaFuncAttributeMaxDynamicSharedMemorySize, SMEM_GEMMH);
    cudaFuncSetAttribute(qkv_gemm,             cudaFuncAttributeMaxDynamicSharedMemorySize, SMEM_GEMMH);
    cudaFuncSetAttribute(tgemm64,              cudaFuncAttributeMaxDynamicSharedMemorySize, SMEM_GEMMH64);

    // Pre-convert + transpose all weights to fp16 [N][Kp] (single launch)
    cvt_trans_kernel<<<(R6 + 255)/256, 256>>>(wq, wk, wv, wo, w1, w2, lm_w, wt);

    {
        int total = MM * (CC/4);
        embed_kernel<<<(total + 255)/256, 256>>>(idx, tok_emb, pos_emb, x);
    }

    for (int L = 0; L < LL; L++) {
        const float* g1  = ln1_g + (size_t)L*CC;
        const float* bg1 = ln1_b + (size_t)L*CC;
        const uint32_t* Wq = wt + OFF16_WQ + (size_t)L*(CC*CC/2);
        const uint32_t* Wk = wt + OFF16_WK + (size_t)L*(CC*CC/2);
        const uint32_t* Wv = wt + OFF16_WV + (size_t)L*(CC*CC/2);
        const uint32_t* Wo = wt + OFF16_WO + (size_t)L*(CC*CC/2);
        const float* Wob = wo_b + (size_t)L*CC;
        const float* g2  = ln2_g + (size_t)L*CC;
        const float* bg2 = ln2_b + (size_t)L*CC;
        const uint32_t* W1 = wt + OFF16_W1 + (size_t)L*(CC*FF/2);
        const float* B1  = b1 + (size_t)L*FF;
        const uint32_t* W2 = wt + OFF16_W2 + (size_t)L*(FF*CC/2);
        const float* B2  = b2 + (size_t)L*CC;

        ln_kernel<<<MM/8, 256>>>(x, g1, bg1, h);
        qkv_gemm<<<dim3(9, 64), 128, SMEM_GEMMH>>>(h, Wq, Wk, Wv, q, k, v);
        attn_mma<<<BB*NH, 256, ATT_SMEM>>>(q, k, v, att);
        // x += att @ Wo + wo_b
        tgemm64<<<dim3(CC/128, MM/64), 128, SMEM_GEMMH64>>>(
            att, Wo, Wob, x, x, MM, CC, CC);
        ln_kernel<<<MM/8, 256>>>(x, g2, bg2, h);
        // u = relu(h @ W1 + b1), fp16 out
        tgemm<true,false,2><<<dim3(FF/128, MM/128), 128, SMEM_GEMMH>>>(
            h, W1, B1, nullptr, u, MM, FF, CC);
        // x += u @ W2 + b2
        tgemm64<<<dim3(CC/128, MM/64), 128, SMEM_GEMMH64>>>(
            u, W2, B2, x, x, MM, CC, FF);
    }

    ln_kernel<<<MM/8, 256>>>(x, lnf_g, lnf_b, h);
    // logits = h @ lm_w + lm_b
    tgemm<false,false,0><<<dim3(VV/128, MM/128), 128, SMEM_GEMMH>>>(
        h, wt + OFF16_LM, lm_b, nullptr, out, MM, VV, CC);
}